// round 5
// baseline (speedup 1.0000x reference)
#include <cuda_runtime.h>
#include <cstdint>

#define NB   128
#define NTH  256

// SMEM float offsets
#define W_OFF    0        // 13312: weights [13][128 k][8 slots]
#define IN_OFF   13312    // 32768: 4-buffered input chunks [4][128][64]
#define RED_OFF  46080    // 9216: reduction 32 rows x 288
#define XS_OFF   55296    // 768
#define BIAS_OFF 56064    // 16
#define BAR_OFF  56080    // 4
#define SMEM_FLOATS 56084
#define SMEM_BYTES  (SMEM_FLOATS*4)

__device__ float    g_rbuf[2][1536*64];   // rates, [k][b]
__device__ float    g_XT[499*128*64];     // X transposed/padded: [s][d(128)][b]
__device__ float    g_Rm1[499*512*64];    // r_m1 history [s][k][b]
__device__ unsigned g_flags[NB*32];       // per-block arrival flags, 128B apart
__device__ unsigned g_bar_gen;            // monotonic generation

__device__ __forceinline__ void cp16(float* sdst, const float* gsrc) {
    unsigned s = (unsigned)__cvta_generic_to_shared(sdst);
    asm volatile("cp.async.cg.shared.global [%0], [%1], 16;\n" :: "r"(s), "l"(gsrc) : "memory");
}

__device__ __forceinline__ void stage(float* dst, const float* src, int tid) {
    for (int i = tid; i < 2048; i += NTH) cp16(dst + i*4, src + i*4);
    asm volatile("cp.async.commit_group;\n" ::: "memory");
}

// Distributed-flag grid barrier: per-block flag (distinct L2 lines), block 0
// aggregates with 127 parallel pollers, single release word. Monotonic across
// graph replays (no resets).
__device__ __forceinline__ void grid_barrier(int g, volatile unsigned* scratch) {
    __syncthreads();
    if (threadIdx.x == 0) {
        __threadfence();
        unsigned gen;
        asm volatile("ld.acquire.gpu.u32 %0,[%1];" : "=r"(gen) : "l"(&g_bar_gen) : "memory");
        unsigned tgt = gen + 1u;
        scratch[0] = tgt;
        asm volatile("st.release.gpu.u32 [%0],%1;" :: "l"(&g_flags[g*32]), "r"(tgt) : "memory");
    }
    __syncthreads();
    const unsigned tgt = scratch[0];
    if (g == 0) {
        if (threadIdx.x < NB - 1) {
            const unsigned* fp = &g_flags[(threadIdx.x + 1)*32];
            unsigned v;
            do { asm volatile("ld.acquire.gpu.u32 %0,[%1];" : "=r"(v) : "l"(fp) : "memory"); }
            while ((int)(v - tgt) < 0);
        }
        __syncthreads();
        if (threadIdx.x == 0)
            asm volatile("st.release.gpu.u32 [%0],%1;" :: "l"(&g_bar_gen), "r"(tgt) : "memory");
    } else {
        if (threadIdx.x == 0) {
            unsigned v;
            do { asm volatile("ld.acquire.gpu.u32 %0,[%1];" : "=r"(v) : "l"(&g_bar_gen) : "memory"); }
            while ((int)(v - tgt) < 0);
        }
        __syncthreads();
    }
}

__device__ __forceinline__ void chunk_fma(float (&acc)[16], const float* rin,
                                          const float* wc, int ks) {
    #pragma unroll
    for (int t = 0; t < 16; t++) {
        int kk = ks*16 + t;
        float4 rv = *(const float4*)(rin + kk*64);
        float4 wv = *(const float4*)(wc + kk*8);
        acc[0]  += rv.x*wv.x; acc[1]  += rv.x*wv.y; acc[2]  += rv.x*wv.z; acc[3]  += rv.x*wv.w;
        acc[4]  += rv.y*wv.x; acc[5]  += rv.y*wv.y; acc[6]  += rv.y*wv.z; acc[7]  += rv.y*wv.w;
        acc[8]  += rv.z*wv.x; acc[9]  += rv.z*wv.y; acc[10] += rv.z*wv.z; acc[11] += rv.z*wv.w;
        acc[12] += rv.w*wv.x; acc[13] += rv.w*wv.y; acc[14] += rv.w*wv.z; acc[15] += rv.w*wv.w;
    }
}

__global__ void __launch_bounds__(NTH, 1)
rnn_kernel(const float* __restrict__ X,
           const float* __restrict__ W_rec_m1, const float* __restrict__ W_rec_pmd,
           const float* __restrict__ W_rec_s1,
           const float* __restrict__ b_m1, const float* __restrict__ b_pmd,
           const float* __restrict__ b_s1,
           const float* __restrict__ W_pmd_m1, const float* __restrict__ W_s1_m1,
           const float* __restrict__ W_m1_pmd,
           const float* __restrict__ W_in_pmd, const float* __restrict__ W_in_s1,
           const float* __restrict__ W_out,
           float* __restrict__ out)
{
    extern __shared__ float sm[];
    const int tid = threadIdx.x;
    const int g   = blockIdx.x;
    float* w_s    = sm + W_OFF;
    float* in_s   = sm + IN_OFF;
    float* red_s  = sm + RED_OFF;
    float* xs     = sm + XS_OFF;
    float* bias_s = sm + BIAS_OFF;
    volatile unsigned* bscr = (volatile unsigned*)(sm + BAR_OFF);
    const int j0  = 4*g;

    // ---- phase 0: init globals ----
    for (int i = g*NTH + tid; i < 2*1536*64; i += NB*NTH) ((float*)g_rbuf)[i] = 0.f;
    for (int i = g*NTH + tid; i < 499*128*64; i += NB*NTH) {
        int b = i & 63, d = (i >> 6) & 127, s = i >> 13;
        g_XT[i] = (d < 100) ? X[((s+1)*64 + b)*100 + d] : 0.f;
    }

    // ---- weights into SMEM: w_s[c][k][slot], slot = jg*4+jj ----
    // c0-3 src r_m1:  jg0=W_m1_pmd(->pmd) jg1=W_rec_m1(->m1)
    // c4-7 src r_pmd: jg0=W_rec_pmd(->pmd) jg1=W_pmd_m1(->m1)
    // c8-11 src r_s1: jg0=W_s1_m1(->m1)   jg1=W_rec_s1(->s1)
    // c12  src Xt:    jg0=W_in_pmd(->pmd) jg1=W_in_s1(->s1)
    for (int idx = tid; idx < 13312; idx += NTH) {
        int c = idx >> 10, rem = idx & 1023, k = rem >> 3, slot = rem & 7;
        int jgq = slot >> 2, jj = slot & 3;
        float v;
        if (c < 4) { int kk = c*128 + k;
            v = jgq ? W_rec_m1[(j0+jj)*512 + kk] : W_m1_pmd[(j0+jj)*512 + kk];
        } else if (c < 8) { int kk = (c-4)*128 + k;
            v = jgq ? W_pmd_m1[(j0+jj)*512 + kk] : W_rec_pmd[(j0+jj)*512 + kk];
        } else if (c < 12) { int kk = (c-8)*128 + k;
            v = jgq ? W_rec_s1[(j0+jj)*512 + kk] : W_s1_m1[(j0+jj)*512 + kk];
        } else {
            v = (k < 100) ? (jgq ? W_in_s1[(j0+jj)*100 + k] : W_in_pmd[(j0+jj)*100 + k]) : 0.f;
        }
        w_s[idx] = v;
    }
    if (tid < 12) {
        int jj = tid & 3;
        bias_s[tid] = (tid < 4) ? b_m1[j0+jj] : ((tid < 8) ? b_pmd[j0+jj] : b_s1[j0+jj]);
    }
    for (int i = tid; i < 768; i += NTH) xs[i] = 0.f;

    grid_barrier(g, bscr);

    const int ks   = tid >> 5;
    const int lane = tid & 31;
    const int jg   = lane >> 4;
    const int b0   = (lane & 15) * 4;

    // ---- the 499-step scan ----
    for (int s = 0; s < 499; s++) {
        const int cur = s & 1;
        const float* rb = g_rbuf[cur];

        // prefetch chunks 0,1 (prefetch distance 2, 4 rotating buffers)
        stage(in_s,         rb,        tid);
        stage(in_s + 8192,  rb + 8192, tid);

        float a0[16], a1[16], a2[16];
        #pragma unroll
        for (int i = 0; i < 16; i++) { a0[i] = 0.f; a1[i] = 0.f; a2[i] = 0.f; }

        for (int c = 0; c < 13; c++) {
            if (c <= 10) {
                const float* src = (c+2 < 12) ? (rb + (c+2)*8192) : (g_XT + s*8192);
                stage(in_s + ((c+2)&3)*8192, src, tid);
                asm volatile("cp.async.wait_group 2;\n" ::: "memory");
            } else if (c == 11) {
                asm volatile("cp.async.wait_group 1;\n" ::: "memory");
            } else {
                asm volatile("cp.async.wait_group 0;\n" ::: "memory");
            }
            __syncthreads();
            const float* rin = in_s + (c&3)*8192 + b0;
            const float* wc  = w_s + c*1024 + jg*4;
            if (c < 8)       chunk_fma(a0, rin, wc, ks);
            else if (c < 12) chunk_fma(a1, rin, wc, ks);
            else             chunk_fma(a2, rin, wc, ks);
        }

        // merge X chunk: jg0 -> pmd(a0 group), jg1 -> s1(a1 group)
        #pragma unroll
        for (int i = 0; i < 16; i++) {
            if (jg == 0) a0[i] += a2[i]; else a1[i] += a2[i];
        }

        // dump partials: red_s[row][e], row stride 288, e = b*4 + (b>>3)*4 (+jj)
        {
            const int rowP = 4*ks + 2*jg, rowS = rowP + 1;
            #pragma unroll
            for (int bi = 0; bi < 4; bi++) {
                int b = b0 + bi;
                int e = b*4 + ((b >> 3) << 2);
                *(float4*)(red_s + rowP*288 + e) = make_float4(a0[bi*4+0], a0[bi*4+1], a0[bi*4+2], a0[bi*4+3]);
                *(float4*)(red_s + rowS*288 + e) = make_float4(a1[bi*4+0], a1[bi*4+1], a1[bi*4+2], a1[bi*4+3]);
            }
        }
        __syncthreads();

        // reduce across 8 K-slice warps, leaky update, tanh, publish
        float* rnew = g_rbuf[cur ^ 1];
        for (int idx = tid; idx < 768; idx += NTH) {
            int col = idx >> 6, b = idx & 63, jj = col & 3;
            int e = b*4 + ((b >> 3) << 2) + jj;
            float sum = 0.f;
            if (col < 4) {            // m1: rows 4q+1 (jg0-S), 4q+2 (jg1-P)
                #pragma unroll
                for (int q = 0; q < 8; q++)
                    sum += red_s[(4*q+1)*288 + e] + red_s[(4*q+2)*288 + e];
            } else if (col < 8) {     // pmd: rows 4q (jg0-P)
                #pragma unroll
                for (int q = 0; q < 8; q++) sum += red_s[(4*q+0)*288 + e];
            } else {                  // s1: rows 4q+3 (jg1-S)
                #pragma unroll
                for (int q = 0; q < 8; q++) sum += red_s[(4*q+3)*288 + e];
            }
            float x = xs[idx];
            x = 0.9f*x + 0.1f*(sum + bias_s[col]);
            xs[idx] = x;
            float r = tanhf(x);
            int grow = (col < 4) ? (j0 + col)
                     : (col < 8) ? (512 + j0 + col - 4)
                                 : (1024 + j0 + col - 8);
            rnew[grow*64 + b] = r;
            if (col < 4) g_Rm1[(s*512 + j0 + col)*64 + b] = r;
        }
        grid_barrier(g, bscr);
    }

    // ---- epilogue: out[t][b][o] = sum_k Rm1[t][k][b] * W_out[o][k] ----
    for (int i = tid; i < 5120; i += NTH) w_s[i] = W_out[i];
    for (int t = g; t < 499; t += NB) {
        float acc3[3] = {0.f, 0.f, 0.f};
        for (int h = 0; h < 2; h++) {
            __syncthreads();
            const float4* src = (const float4*)(g_Rm1 + (t*512 + h*256)*64);
            for (int i = tid; i < 4096; i += NTH) ((float4*)in_s)[i] = src[i];
            __syncthreads();
            #pragma unroll
            for (int pi = 0; pi < 3; pi++) {
                int p = tid + pi*256;
                if (p < 640) {
                    int o = p >> 6, b = p & 63;
                    float sv = 0.f;
                    #pragma unroll 8
                    for (int k = 0; k < 256; k++)
                        sv += in_s[k*64 + b] * w_s[o*512 + h*256 + k];
                    acc3[pi] += sv;
                }
            }
        }
        #pragma unroll
        for (int pi = 0; pi < 3; pi++) {
            int p = tid + pi*256;
            if (p < 640) {
                int o = p >> 6, b = p & 63;
                out[t*640 + b*10 + o] = acc3[pi];
            }
        }
    }
}

extern "C" void kernel_launch(void* const* d_in, const int* in_sizes, int n_in,
                              void* d_out, int out_size) {
    cudaFuncSetAttribute(rnn_kernel, cudaFuncAttributeMaxDynamicSharedMemorySize, SMEM_BYTES);
    rnn_kernel<<<NB, NTH, SMEM_BYTES>>>(
        (const float*)d_in[0],  (const float*)d_in[1],  (const float*)d_in[2],
        (const float*)d_in[3],  (const float*)d_in[4],  (const float*)d_in[5],
        (const float*)d_in[6],  (const float*)d_in[7],  (const float*)d_in[8],
        (const float*)d_in[9],  (const float*)d_in[10], (const float*)d_in[11],
        (const float*)d_in[12], (float*)d_out);
}

// round 6
// speedup vs baseline: 1.0163x; 1.0163x over previous
#include <cuda_runtime.h>
#include <cstdint>

#define NB   128
#define NTH  512

// SMEM float offsets
#define W_OFF    0        // 13312: weights [13][128 k][8 slots]
#define IN_OFF   13312    // 16384: double-buffered input chunk [2][128][64]
#define RED_OFF  29696    // 18432: reduction 64 rows x 288
#define XS_OFF   48128    // 768
#define BIAS_OFF 48896    // 16
#define SMEM_FLOATS 48912
#define SMEM_BYTES  (SMEM_FLOATS*4)

__device__ float    g_rbuf[2][1536*64];   // rates, [k][b]
__device__ float    g_XT[499*128*64];     // X transposed/padded: [s][d(128)][b]
__device__ float    g_Rm1[499*512*64];    // r_m1 history [s][k][b]
__device__ unsigned g_bar_count;
__device__ unsigned g_bar_gen;

__device__ __forceinline__ void cp16(float* sdst, const float* gsrc) {
    unsigned s = (unsigned)__cvta_generic_to_shared(sdst);
    asm volatile("cp.async.cg.shared.global [%0], [%1], 16;\n" :: "r"(s), "l"(gsrc) : "memory");
}

__device__ __forceinline__ void stage(float* dst, const float* src, int tid) {
    for (int i = tid; i < 2048; i += NTH) cp16(dst + i*4, src + i*4);
    asm volatile("cp.async.commit_group;\n" ::: "memory");
}

// simple central-atomic grid barrier (best measured); monotonic gen, replay-safe
__device__ __forceinline__ void grid_barrier() {
    __syncthreads();
    if (threadIdx.x == 0) {
        __threadfence();
        unsigned old = *(volatile unsigned*)&g_bar_gen;
        if (atomicAdd(&g_bar_count, 1u) == NB - 1u) {
            atomicExch(&g_bar_count, 0u);
            __threadfence();
            atomicAdd(&g_bar_gen, 1u);
        } else {
            while (*(volatile unsigned*)&g_bar_gen == old) { }
        }
    }
    __syncthreads();
}

// 8 k-iters per K-slice (16 slices across 16 warps)
__device__ __forceinline__ void chunk_fma(float (&acc)[16], const float* rin,
                                          const float* wc, int ks) {
    #pragma unroll
    for (int t = 0; t < 8; t++) {
        int kk = ks*8 + t;
        float4 rv = *(const float4*)(rin + kk*64);
        float4 wv = *(const float4*)(wc + kk*8);
        acc[0]  += rv.x*wv.x; acc[1]  += rv.x*wv.y; acc[2]  += rv.x*wv.z; acc[3]  += rv.x*wv.w;
        acc[4]  += rv.y*wv.x; acc[5]  += rv.y*wv.y; acc[6]  += rv.y*wv.z; acc[7]  += rv.y*wv.w;
        acc[8]  += rv.z*wv.x; acc[9]  += rv.z*wv.y; acc[10] += rv.z*wv.z; acc[11] += rv.z*wv.w;
        acc[12] += rv.w*wv.x; acc[13] += rv.w*wv.y; acc[14] += rv.w*wv.z; acc[15] += rv.w*wv.w;
    }
}

__global__ void __launch_bounds__(NTH, 1)
rnn_kernel(const float* __restrict__ X,
           const float* __restrict__ W_rec_m1, const float* __restrict__ W_rec_pmd,
           const float* __restrict__ W_rec_s1,
           const float* __restrict__ b_m1, const float* __restrict__ b_pmd,
           const float* __restrict__ b_s1,
           const float* __restrict__ W_pmd_m1, const float* __restrict__ W_s1_m1,
           const float* __restrict__ W_m1_pmd,
           const float* __restrict__ W_in_pmd, const float* __restrict__ W_in_s1,
           const float* __restrict__ W_out,
           float* __restrict__ out)
{
    extern __shared__ float sm[];
    const int tid = threadIdx.x;
    const int g   = blockIdx.x;
    float* w_s    = sm + W_OFF;
    float* in_s   = sm + IN_OFF;
    float* red_s  = sm + RED_OFF;
    float* xs     = sm + XS_OFF;
    float* bias_s = sm + BIAS_OFF;
    const int j0  = 4*g;

    // ---- phase 0: init globals ----
    for (int i = g*NTH + tid; i < 2*1536*64; i += NB*NTH) ((float*)g_rbuf)[i] = 0.f;
    for (int i = g*NTH + tid; i < 499*128*64; i += NB*NTH) {
        int b = i & 63, d = (i >> 6) & 127, s = i >> 13;
        g_XT[i] = (d < 100) ? X[((s+1)*64 + b)*100 + d] : 0.f;
    }

    // ---- weights into SMEM: w_s[c][k][slot], slot = jg*4+jj ----
    // c0-3 src r_m1:  jg0=W_m1_pmd(->pmd) jg1=W_rec_m1(->m1)
    // c4-7 src r_pmd: jg0=W_rec_pmd(->pmd) jg1=W_pmd_m1(->m1)
    // c8-11 src r_s1: jg0=W_s1_m1(->m1)   jg1=W_rec_s1(->s1)
    // c12  src Xt:    jg0=W_in_pmd(->pmd) jg1=W_in_s1(->s1)
    for (int idx = tid; idx < 13312; idx += NTH) {
        int c = idx >> 10, rem = idx & 1023, k = rem >> 3, slot = rem & 7;
        int jgq = slot >> 2, jj = slot & 3;
        float v;
        if (c < 4) { int kk = c*128 + k;
            v = jgq ? W_rec_m1[(j0+jj)*512 + kk] : W_m1_pmd[(j0+jj)*512 + kk];
        } else if (c < 8) { int kk = (c-4)*128 + k;
            v = jgq ? W_pmd_m1[(j0+jj)*512 + kk] : W_rec_pmd[(j0+jj)*512 + kk];
        } else if (c < 12) { int kk = (c-8)*128 + k;
            v = jgq ? W_rec_s1[(j0+jj)*512 + kk] : W_s1_m1[(j0+jj)*512 + kk];
        } else {
            v = (k < 100) ? (jgq ? W_in_s1[(j0+jj)*100 + k] : W_in_pmd[(j0+jj)*100 + k]) : 0.f;
        }
        w_s[idx] = v;
    }
    if (tid < 12) {
        int jj = tid & 3;
        bias_s[tid] = (tid < 4) ? b_m1[j0+jj] : ((tid < 8) ? b_pmd[j0+jj] : b_s1[j0+jj]);
    }
    for (int i = tid; i < 768; i += NTH) xs[i] = 0.f;

    grid_barrier();

    const int ks   = tid >> 5;          // 0..15 K-slices
    const int lane = tid & 31;
    const int jg   = lane >> 4;
    const int b0   = (lane & 15) * 4;

    // ---- the 499-step scan ----
    for (int s = 0; s < 499; s++) {
        const int cur = s & 1;
        const float* rb = g_rbuf[cur];

        stage(in_s, rb, tid);
        asm volatile("cp.async.wait_group 0;\n" ::: "memory");
        __syncthreads();

        float a0[16], a1[16], a2[16];
        #pragma unroll
        for (int i = 0; i < 16; i++) { a0[i] = 0.f; a1[i] = 0.f; a2[i] = 0.f; }

        for (int c = 0; c < 8; c++) {
            stage(in_s + ((c+1)&1)*8192, rb + (c+1)*8192, tid);
            chunk_fma(a0, in_s + (c&1)*8192 + b0, w_s + c*1024 + jg*4, ks);
            asm volatile("cp.async.wait_group 0;\n" ::: "memory");
            __syncthreads();
        }
        for (int c = 8; c < 12; c++) {
            const float* src = (c < 11) ? (rb + (c+1)*8192) : (g_XT + s*8192);
            stage(in_s + ((c+1)&1)*8192, src, tid);
            chunk_fma(a1, in_s + (c&1)*8192 + b0, w_s + c*1024 + jg*4, ks);
            asm volatile("cp.async.wait_group 0;\n" ::: "memory");
            __syncthreads();
        }
        chunk_fma(a2, in_s + 0*8192 + b0, w_s + 12*1024 + jg*4, ks);

        // merge X chunk: jg0 -> pmd(a0), jg1 -> s1(a1)
        #pragma unroll
        for (int i = 0; i < 16; i++) {
            if (jg == 0) a0[i] += a2[i]; else a1[i] += a2[i];
        }

        // dump partials: red_s[row][e], row stride 288, e = b*4 + (b>>3)*4 (+jj)
        {
            const int rowP = 4*ks + 2*jg, rowS = rowP + 1;
            #pragma unroll
            for (int bi = 0; bi < 4; bi++) {
                int b = b0 + bi;
                int e = b*4 + ((b >> 3) << 2);
                *(float4*)(red_s + rowP*288 + e) = make_float4(a0[bi*4+0], a0[bi*4+1], a0[bi*4+2], a0[bi*4+3]);
                *(float4*)(red_s + rowS*288 + e) = make_float4(a1[bi*4+0], a1[bi*4+1], a1[bi*4+2], a1[bi*4+3]);
            }
        }
        __syncthreads();

        // reduce across 16 K-slice warps, leaky update, tanh, publish
        float* rnew = g_rbuf[cur ^ 1];
        for (int idx = tid; idx < 768; idx += NTH) {
            int col = idx >> 6, b = idx & 63, jj = col & 3;
            int e = b*4 + ((b >> 3) << 2) + jj;
            float sum = 0.f;
            if (col < 4) {            // m1: rows 4q+1 (jg0-S), 4q+2 (jg1-P)
                #pragma unroll
                for (int q = 0; q < 16; q++)
                    sum += red_s[(4*q+1)*288 + e] + red_s[(4*q+2)*288 + e];
            } else if (col < 8) {     // pmd: rows 4q (jg0-P)
                #pragma unroll
                for (int q = 0; q < 16; q++) sum += red_s[(4*q+0)*288 + e];
            } else {                  // s1: rows 4q+3 (jg1-S)
                #pragma unroll
                for (int q = 0; q < 16; q++) sum += red_s[(4*q+3)*288 + e];
            }
            float x = xs[idx];
            x = 0.9f*x + 0.1f*(sum + bias_s[col]);
            xs[idx] = x;
            float r = tanhf(x);
            int grow = (col < 4) ? (j0 + col)
                     : (col < 8) ? (512 + j0 + col - 4)
                                 : (1024 + j0 + col - 8);
            rnew[grow*64 + b] = r;
            if (col < 4) g_Rm1[(s*512 + j0 + col)*64 + b] = r;
        }
        grid_barrier();
    }

    // ---- epilogue: out[t][b][o] = sum_k Rm1[t][k][b] * W_out[o][k] ----
    for (int i = tid; i < 5120; i += NTH) w_s[i] = W_out[i];
    for (int t = g; t < 499; t += NB) {
        float acc2[2] = {0.f, 0.f};
        for (int h = 0; h < 2; h++) {
            __syncthreads();
            const float4* src = (const float4*)(g_Rm1 + (t*512 + h*256)*64);
            for (int i = tid; i < 4096; i += NTH) ((float4*)in_s)[i] = src[i];
            __syncthreads();
            #pragma unroll
            for (int pi = 0; pi < 2; pi++) {
                int p = tid + pi*NTH;
                if (p < 640) {
                    int o = p >> 6, b = p & 63;
                    float sv = 0.f;
                    #pragma unroll 8
                    for (int k = 0; k < 256; k++)
                        sv += in_s[k*64 + b] * w_s[o*512 + h*256 + k];
                    acc2[pi] += sv;
                }
            }
        }
        #pragma unroll
        for (int pi = 0; pi < 2; pi++) {
            int p = tid + pi*NTH;
            if (p < 640) {
                int o = p >> 6, b = p & 63;
                out[t*640 + b*10 + o] = acc2[pi];
            }
        }
    }
}

extern "C" void kernel_launch(void* const* d_in, const int* in_sizes, int n_in,
                              void* d_out, int out_size) {
    cudaFuncSetAttribute(rnn_kernel, cudaFuncAttributeMaxDynamicSharedMemorySize, SMEM_BYTES);
    rnn_kernel<<<NB, NTH, SMEM_BYTES>>>(
        (const float*)d_in[0],  (const float*)d_in[1],  (const float*)d_in[2],
        (const float*)d_in[3],  (const float*)d_in[4],  (const float*)d_in[5],
        (const float*)d_in[6],  (const float*)d_in[7],  (const float*)d_in[8],
        (const float*)d_in[9],  (const float*)d_in[10], (const float*)d_in[11],
        (const float*)d_in[12], (float*)d_out);
}

// round 7
// speedup vs baseline: 1.2405x; 1.2206x over previous
#include <cuda_runtime.h>
#include <cstdint>

#define NB   128
#define NTH  256

// SMEM float offsets
#define W_OFF    0        // 13312: weights [kabs 0..1663][8 slots]
#define IN_OFF   13312    // 32768: double-buffered 256k-chunk [2][256][64]
#define RED_OFF  46080    // 9216: reduction 32 rows x 288
#define XS_OFF   55296    // 768
#define BIAS_OFF 56064    // 16
#define SMEM_FLOATS 56080
#define SMEM_BYTES  (SMEM_FLOATS*4)

__device__ float    g_rbuf[2][1536*64];   // rates, [k][b]
__device__ float    g_XT[499*128*64];     // X transposed/padded: [s][d(128)][b]
__device__ float    g_Rm1[499*512*64];    // r_m1 history [s][k][b]
__device__ unsigned g_bar_count;
__device__ unsigned g_bar_gen;

__device__ __forceinline__ void cp16(float* sdst, const float* gsrc) {
    unsigned s = (unsigned)__cvta_generic_to_shared(sdst);
    asm volatile("cp.async.cg.shared.global [%0], [%1], 16;\n" :: "r"(s), "l"(gsrc) : "memory");
}

// stage n16*16 bytes, one commit group
__device__ __forceinline__ void stage_n(float* dst, const float* src, int tid, int n16) {
    for (int i = tid; i < n16; i += NTH) cp16(dst + i*4, src + i*4);
    asm volatile("cp.async.commit_group;\n" ::: "memory");
}

#define WAITG(n) asm volatile("cp.async.wait_group %0;\n" :: "n"(n) : "memory")

// central-atomic grid barrier (best measured); monotonic gen, replay-safe
__device__ __forceinline__ void grid_barrier() {
    __syncthreads();
    if (threadIdx.x == 0) {
        __threadfence();
        unsigned old = *(volatile unsigned*)&g_bar_gen;
        if (atomicAdd(&g_bar_count, 1u) == NB - 1u) {
            atomicExch(&g_bar_count, 0u);
            __threadfence();
            atomicAdd(&g_bar_gen, 1u);
        } else {
            while (*(volatile unsigned*)&g_bar_gen == old) { }
        }
    }
    __syncthreads();
}

// KS k-iters per warp slice (8 warps)
template<int KS>
__device__ __forceinline__ void chunk_fma(float (&acc)[16], const float* rin,
                                          const float* wc, int ks) {
    #pragma unroll
    for (int t = 0; t < KS; t++) {
        int kk = ks*KS + t;
        float4 rv = *(const float4*)(rin + kk*64);
        float4 wv = *(const float4*)(wc + kk*8);
        acc[0]  += rv.x*wv.x; acc[1]  += rv.x*wv.y; acc[2]  += rv.x*wv.z; acc[3]  += rv.x*wv.w;
        acc[4]  += rv.y*wv.x; acc[5]  += rv.y*wv.y; acc[6]  += rv.y*wv.z; acc[7]  += rv.y*wv.w;
        acc[8]  += rv.z*wv.x; acc[9]  += rv.z*wv.y; acc[10] += rv.z*wv.z; acc[11] += rv.z*wv.w;
        acc[12] += rv.w*wv.x; acc[13] += rv.w*wv.y; acc[14] += rv.w*wv.z; acc[15] += rv.w*wv.w;
    }
}

__global__ void __launch_bounds__(NTH, 1)
rnn_kernel(const float* __restrict__ X,
           const float* __restrict__ W_rec_m1, const float* __restrict__ W_rec_pmd,
           const float* __restrict__ W_rec_s1,
           const float* __restrict__ b_m1, const float* __restrict__ b_pmd,
           const float* __restrict__ b_s1,
           const float* __restrict__ W_pmd_m1, const float* __restrict__ W_s1_m1,
           const float* __restrict__ W_m1_pmd,
           const float* __restrict__ W_in_pmd, const float* __restrict__ W_in_s1,
           const float* __restrict__ W_out,
           float* __restrict__ out)
{
    extern __shared__ float sm[];
    const int tid = threadIdx.x;
    const int g   = blockIdx.x;
    float* w_s    = sm + W_OFF;
    float* in_s   = sm + IN_OFF;
    float* red_s  = sm + RED_OFF;
    float* xs     = sm + XS_OFF;
    float* bias_s = sm + BIAS_OFF;
    const int j0  = 4*g;

    // ---- phase 0: init globals ----
    for (int i = g*NTH + tid; i < 2*1536*64; i += NB*NTH) ((float*)g_rbuf)[i] = 0.f;
    for (int i = g*NTH + tid; i < 499*128*64; i += NB*NTH) {
        int b = i & 63, d = (i >> 6) & 127, s = i >> 13;
        g_XT[i] = (d < 100) ? X[((s+1)*64 + b)*100 + d] : 0.f;
    }

    // ---- weights into SMEM: w_s[kabs][slot], slot = jg*4+jj; kabs = c*128+k legacy fill ----
    // kabs 0-511 src r_m1:    jg0=W_m1_pmd(->pmd) jg1=W_rec_m1(->m1)
    // kabs 512-1023 src r_pmd: jg0=W_rec_pmd(->pmd) jg1=W_pmd_m1(->m1)
    // kabs 1024-1535 src r_s1: jg0=W_s1_m1(->m1)   jg1=W_rec_s1(->s1)
    // kabs 1536-1663 src Xt:   jg0=W_in_pmd(->pmd) jg1=W_in_s1(->s1)
    for (int idx = tid; idx < 13312; idx += NTH) {
        int c = idx >> 10, rem = idx & 1023, k = rem >> 3, slot = rem & 7;
        int jgq = slot >> 2, jj = slot & 3;
        float v;
        if (c < 4) { int kk = c*128 + k;
            v = jgq ? W_rec_m1[(j0+jj)*512 + kk] : W_m1_pmd[(j0+jj)*512 + kk];
        } else if (c < 8) { int kk = (c-4)*128 + k;
            v = jgq ? W_pmd_m1[(j0+jj)*512 + kk] : W_rec_pmd[(j0+jj)*512 + kk];
        } else if (c < 12) { int kk = (c-8)*128 + k;
            v = jgq ? W_rec_s1[(j0+jj)*512 + kk] : W_s1_m1[(j0+jj)*512 + kk];
        } else {
            v = (k < 100) ? (jgq ? W_in_s1[(j0+jj)*100 + k] : W_in_pmd[(j0+jj)*100 + k]) : 0.f;
        }
        w_s[idx] = v;
    }
    if (tid < 12) {
        int jj = tid & 3;
        bias_s[tid] = (tid < 4) ? b_m1[j0+jj] : ((tid < 8) ? b_pmd[j0+jj] : b_s1[j0+jj]);
    }
    for (int i = tid; i < 768; i += NTH) xs[i] = 0.f;

    grid_barrier();

    const int ks   = tid >> 5;          // 0..7 K-slices
    const int lane = tid & 31;
    const int jg   = lane >> 4;
    const int b0   = (lane & 15) * 4;

    // pre-stage X(0) into buf0 (group A)
    stage_n(in_s, g_XT, tid, 2048);

    // ---- the 499-step scan ----
    for (int s = 0; s < 499; s++) {
        const int cur = s & 1;
        const float* rb = g_rbuf[cur];

        float a0[16], a1[16], a2[16];
        #pragma unroll
        for (int i = 0; i < 16; i++) { a0[i] = 0.f; a1[i] = 0.f; a2[i] = 0.f; }

        // stage c1 (r[0:256k) -> buf1), then compute X (buf0) once X arrived
        stage_n(in_s + 16384, rb, tid, 4096);
        WAITG(1);                 // X (group A) done; c1 flying
        __syncthreads();
        chunk_fma<16>(a2, in_s + b0, w_s + 12288 + jg*4, ks);
        WAITG(0);                 // c1 done
        __syncthreads();          // also: buf0 free for c2 staging

        // rounds c=1..6: chunk c covers kabs [(c-1)*256, c*256)
        #pragma unroll
        for (int c = 1; c <= 6; c++) {
            if (c < 6) stage_n(in_s + ((c+1)&1)*16384, rb + c*16384, tid, 4096);
            const float* rin = in_s + (c&1)*16384 + b0;
            const float* wc  = w_s + (c-1)*2048 + jg*4;
            if (c <= 4) chunk_fma<32>(a0, rin, wc, ks);
            else        chunk_fma<32>(a1, rin, wc, ks);
            if (c < 6) { WAITG(0); __syncthreads(); }
        }

        // merge X round: jg0 -> pmd(a0 group), jg1 -> s1(a1 group)
        #pragma unroll
        for (int i = 0; i < 16; i++) {
            if (jg == 0) a0[i] += a2[i]; else a1[i] += a2[i];
        }

        // dump partials: red_s[row][e], row stride 288, e = b*4 + (b>>3)*4 (+jj)
        {
            const int rowP = 4*ks + 2*jg, rowS = rowP + 1;
            #pragma unroll
            for (int bi = 0; bi < 4; bi++) {
                int b = b0 + bi;
                int e = b*4 + ((b >> 3) << 2);
                *(float4*)(red_s + rowP*288 + e) = make_float4(a0[bi*4+0], a0[bi*4+1], a0[bi*4+2], a0[bi*4+3]);
                *(float4*)(red_s + rowS*288 + e) = make_float4(a1[bi*4+0], a1[bi*4+1], a1[bi*4+2], a1[bi*4+3]);
            }
        }
        __syncthreads();

        // reduce across 8 K-slice warps, leaky update, tanh, publish
        float* rnew = g_rbuf[cur ^ 1];
        for (int idx = tid; idx < 768; idx += NTH) {
            int col = idx >> 6, b = idx & 63, jj = col & 3;
            int e = b*4 + ((b >> 3) << 2) + jj;
            float sum = 0.f;
            if (col < 4) {            // m1: rows 4q+1 (jg0-S), 4q+2 (jg1-P)
                #pragma unroll
                for (int q = 0; q < 8; q++)
                    sum += red_s[(4*q+1)*288 + e] + red_s[(4*q+2)*288 + e];
            } else if (col < 8) {     // pmd: rows 4q (jg0-P)
                #pragma unroll
                for (int q = 0; q < 8; q++) sum += red_s[(4*q+0)*288 + e];
            } else {                  // s1: rows 4q+3 (jg1-S)
                #pragma unroll
                for (int q = 0; q < 8; q++) sum += red_s[(4*q+3)*288 + e];
            }
            float x = xs[idx];
            x = 0.9f*x + 0.1f*(sum + bias_s[col]);
            xs[idx] = x;
            float r = tanhf(x);
            int grow = (col < 4) ? (j0 + col)
                     : (col < 8) ? (512 + j0 + col - 4)
                                 : (1024 + j0 + col - 8);
            rnew[grow*64 + b] = r;
            if (col < 4) g_Rm1[(s*512 + j0 + col)*64 + b] = r;
        }

        // pre-stage X(s+1) into buf0 (rides through the barrier)
        if (s < 498) stage_n(in_s, g_XT + (s+1)*8192, tid, 2048);

        grid_barrier();
    }

    // ---- epilogue: out[t][b][o] = sum_k Rm1[t][k][b] * W_out[o][k] ----
    for (int i = tid; i < 5120; i += NTH) w_s[i] = W_out[i];
    for (int t = g; t < 499; t += NB) {
        float acc3[3] = {0.f, 0.f, 0.f};
        for (int h = 0; h < 2; h++) {
            __syncthreads();
            const float4* src = (const float4*)(g_Rm1 + (t*512 + h*256)*64);
            for (int i = tid; i < 4096; i += NTH) ((float4*)in_s)[i] = src[i];
            __syncthreads();
            #pragma unroll
            for (int pi = 0; pi < 3; pi++) {
                int p = tid + pi*256;
                if (p < 640) {
                    int o = p >> 6, b = p & 63;
                    float sv = 0.f;
                    #pragma unroll 8
                    for (int k = 0; k < 256; k++)
                        sv += in_s[k*64 + b] * w_s[o*512 + h*256 + k];
                    acc3[pi] += sv;
                }
            }
        }
        #pragma unroll
        for (int pi = 0; pi < 3; pi++) {
            int p = tid + pi*256;
            if (p < 640) {
                int o = p >> 6, b = p & 63;
                out[t*640 + b*10 + o] = acc3[pi];
            }
        }
    }
}

extern "C" void kernel_launch(void* const* d_in, const int* in_sizes, int n_in,
                              void* d_out, int out_size) {
    cudaFuncSetAttribute(rnn_kernel, cudaFuncAttributeMaxDynamicSharedMemorySize, SMEM_BYTES);
    rnn_kernel<<<NB, NTH, SMEM_BYTES>>>(
        (const float*)d_in[0],  (const float*)d_in[1],  (const float*)d_in[2],
        (const float*)d_in[3],  (const float*)d_in[4],  (const float*)d_in[5],
        (const float*)d_in[6],  (const float*)d_in[7],  (const float*)d_in[8],
        (const float*)d_in[9],  (const float*)d_in[10], (const float*)d_in[11],
        (const float*)d_in[12], (float*)d_out);
}

// round 8
// speedup vs baseline: 1.2632x; 1.0183x over previous
#include <cuda_runtime.h>
#include <cstdint>

#define NB   128
#define NTH  256

// SMEM float offsets
#define W_OFF    0        // 13312: weights [kabs 0..1663][8 slots]
#define IN_OFF   13312    // 32768: double-buffered 256k-chunk [2][256][64] (warp-private rows)
#define RED_OFF  46080    // 9216: reduction 32 rows x 288
#define XS_OFF   55296    // 768
#define BIAS_OFF 56064    // 16
#define SMEM_FLOATS 56080
#define SMEM_BYTES  (SMEM_FLOATS*4)

__device__ float    g_rbuf[2][1536*64];   // rates, [k][b]
__device__ float    g_XT[499*128*64];     // X transposed/padded: [s][d(128)][b]
__device__ float    g_Rm1[499*512*64];    // r_m1 history [s][k][b]
__device__ unsigned g_bar_count;
__device__ unsigned g_bar_gen;

__device__ __forceinline__ void cp16(float* sdst, const float* gsrc) {
    unsigned s = (unsigned)__cvta_generic_to_shared(sdst);
    asm volatile("cp.async.cg.shared.global [%0], [%1], 16;\n" :: "r"(s), "l"(gsrc) : "memory");
}
#define WAITG(n) asm volatile("cp.async.wait_group %0;\n" :: "n"(n) : "memory")
#define COMMIT   asm volatile("cp.async.commit_group;\n" ::: "memory")

// warp-private staging: warp ks copies its own 32 rows (2048 floats) of a chunk
__device__ __forceinline__ void stage_chunk(float* dstbuf, const float* srcchunk,
                                            int ks, int lane) {
    const float* src = srcchunk + ks*2048;
    float*       dst = dstbuf   + ks*2048;
    #pragma unroll
    for (int q = 0; q < 16; q++) { int i = q*32 + lane; cp16(dst + i*4, src + i*4); }
    COMMIT;
}
// X chunk: warp ks copies its 16 rows (1024 floats) into ITS OWN buffer region
__device__ __forceinline__ void stage_x(float* dstbuf, const float* srcx,
                                        int ks, int lane) {
    const float* src = srcx   + ks*1024;
    float*       dst = dstbuf + ks*2048;
    #pragma unroll
    for (int q = 0; q < 8; q++) { int i = q*32 + lane; cp16(dst + i*4, src + i*4); }
    COMMIT;
}

// KS k-iters; rin pre-offset to warp region (+b0), wc pre-offset to warp k-slice (+jg*4)
template<int KS>
__device__ __forceinline__ void chunk_fma(float (&acc)[16], const float* rin,
                                          const float* wc) {
    #pragma unroll
    for (int t = 0; t < KS; t++) {
        float4 rv = *(const float4*)(rin + t*64);
        float4 wv = *(const float4*)(wc + t*8);
        acc[0]  += rv.x*wv.x; acc[1]  += rv.x*wv.y; acc[2]  += rv.x*wv.z; acc[3]  += rv.x*wv.w;
        acc[4]  += rv.y*wv.x; acc[5]  += rv.y*wv.y; acc[6]  += rv.y*wv.z; acc[7]  += rv.y*wv.w;
        acc[8]  += rv.z*wv.x; acc[9]  += rv.z*wv.y; acc[10] += rv.z*wv.z; acc[11] += rv.z*wv.w;
        acc[12] += rv.w*wv.x; acc[13] += rv.w*wv.y; acc[14] += rv.w*wv.z; acc[15] += rv.w*wv.w;
    }
}

__global__ void __launch_bounds__(NTH, 1)
rnn_kernel(const float* __restrict__ X,
           const float* __restrict__ W_rec_m1, const float* __restrict__ W_rec_pmd,
           const float* __restrict__ W_rec_s1,
           const float* __restrict__ b_m1, const float* __restrict__ b_pmd,
           const float* __restrict__ b_s1,
           const float* __restrict__ W_pmd_m1, const float* __restrict__ W_s1_m1,
           const float* __restrict__ W_m1_pmd,
           const float* __restrict__ W_in_pmd, const float* __restrict__ W_in_s1,
           const float* __restrict__ W_out,
           float* __restrict__ out)
{
    extern __shared__ float sm[];
    const int tid = threadIdx.x;
    const int g   = blockIdx.x;
    float* w_s    = sm + W_OFF;
    float* in_s   = sm + IN_OFF;
    float* red_s  = sm + RED_OFF;
    float* xs     = sm + XS_OFF;
    float* bias_s = sm + BIAS_OFF;
    const int j0  = 4*g;

    // ---- phase 0: init globals ----
    for (int i = g*NTH + tid; i < 2*1536*64; i += NB*NTH) ((float*)g_rbuf)[i] = 0.f;
    for (int i = g*NTH + tid; i < 499*128*64; i += NB*NTH) {
        int b = i & 63, d = (i >> 6) & 127, s = i >> 13;
        g_XT[i] = (d < 100) ? X[((s+1)*64 + b)*100 + d] : 0.f;
    }

    // ---- weights into SMEM: w_s[kabs][slot], slot = jg*4+jj ----
    // kabs 0-511 (r_m1):    jg0=W_m1_pmd(->pmd) jg1=W_rec_m1(->m1)
    // kabs 512-1023 (r_pmd): jg0=W_rec_pmd(->pmd) jg1=W_pmd_m1(->m1)
    // kabs 1024-1535 (r_s1): jg0=W_s1_m1(->m1)   jg1=W_rec_s1(->s1)
    // kabs 1536-1663 (Xt):   jg0=W_in_pmd(->pmd) jg1=W_in_s1(->s1)
    for (int idx = tid; idx < 13312; idx += NTH) {
        int c = idx >> 10, rem = idx & 1023, k = rem >> 3, slot = rem & 7;
        int jgq = slot >> 2, jj = slot & 3;
        float v;
        if (c < 4) { int kk = c*128 + k;
            v = jgq ? W_rec_m1[(j0+jj)*512 + kk] : W_m1_pmd[(j0+jj)*512 + kk];
        } else if (c < 8) { int kk = (c-4)*128 + k;
            v = jgq ? W_pmd_m1[(j0+jj)*512 + kk] : W_rec_pmd[(j0+jj)*512 + kk];
        } else if (c < 12) { int kk = (c-8)*128 + k;
            v = jgq ? W_rec_s1[(j0+jj)*512 + kk] : W_s1_m1[(j0+jj)*512 + kk];
        } else {
            v = (k < 100) ? (jgq ? W_in_s1[(j0+jj)*100 + k] : W_in_pmd[(j0+jj)*100 + k]) : 0.f;
        }
        w_s[idx] = v;
    }
    if (tid < 12) {
        int jj = tid & 3;
        bias_s[tid] = (tid < 4) ? b_m1[j0+jj] : ((tid < 8) ? b_pmd[j0+jj] : b_s1[j0+jj]);
    }
    for (int i = tid; i < 768; i += NTH) xs[i] = 0.f;

    // full initial grid barrier
    __syncthreads();
    if (tid == 0) {
        __threadfence();
        unsigned old = *(volatile unsigned*)&g_bar_gen;
        if (atomicAdd(&g_bar_count, 1u) == NB - 1u) {
            atomicExch(&g_bar_count, 0u);
            __threadfence();
            atomicAdd(&g_bar_gen, 1u);
        } else {
            while (*(volatile unsigned*)&g_bar_gen == old) { }
        }
    }
    __syncthreads();

    const int ks   = tid >> 5;          // 0..7 K-slices
    const int lane = tid & 31;
    const int jg   = lane >> 4;
    const int b0   = (lane & 15) * 4;
    const float* rwp = in_s + ks*2048 + b0;          // warp region in buf0 (+16384 for buf1)
    const float* wxc = w_s + 12288 + ks*128 + jg*4;  // X weight slice

    // prologue: stage + compute X(0) contribution
    float a2[16];
    #pragma unroll
    for (int i = 0; i < 16; i++) a2[i] = 0.f;
    stage_x(in_s, g_XT, ks, lane);
    WAITG(0); __syncwarp();
    chunk_fma<16>(a2, rwp, wxc);

    unsigned bar_old = 0, bar_prev = 0;

    // ---- the 499-step scan ----
    for (int s = 0; s < 499; s++) {
        const float* rb = g_rbuf[s & 1];

        float a0[16], a1[16];
        #pragma unroll
        for (int i = 0; i < 16; i++) { a0[i] = 0.f; a1[i] = 0.f; }

        // chunk c covers kabs [(c-1)*256, c*256); warp-private rounds, no syncthreads
        stage_chunk(in_s + 16384, rb, ks, lane);          // c1 -> buf1
        #pragma unroll
        for (int c = 1; c <= 6; c++) {
            if (c < 6) stage_chunk(in_s + (((c+1)&1)<<14), rb + c*16384, ks, lane);
            if (c < 6) { WAITG(1); } else { WAITG(0); }
            __syncwarp();
            const float* rin = in_s + ((c&1)<<14) + ks*2048 + b0;
            const float* wc  = w_s + (c-1)*2048 + ks*256 + jg*4;
            if (c <= 4) chunk_fma<32>(a0, rin, wc);
            else        chunk_fma<32>(a1, rin, wc);
        }

        // merge X contribution: jg0 -> pmd(a0), jg1 -> s1(a1)
        #pragma unroll
        for (int i = 0; i < 16; i++) {
            if (jg == 0) a0[i] += a2[i]; else a1[i] += a2[i];
        }

        // dump partials: red_s[row][e], row stride 288, e = b*4 + (b>>3)*4 (+jj)
        {
            const int rowP = 4*ks + 2*jg, rowS = rowP + 1;
            #pragma unroll
            for (int bi = 0; bi < 4; bi++) {
                int b = b0 + bi;
                int e = b*4 + ((b >> 3) << 2);
                *(float4*)(red_s + rowP*288 + e) = make_float4(a0[bi*4+0], a0[bi*4+1], a0[bi*4+2], a0[bi*4+3]);
                *(float4*)(red_s + rowS*288 + e) = make_float4(a1[bi*4+0], a1[bi*4+1], a1[bi*4+2], a1[bi*4+3]);
            }
        }
        __syncthreads();

        // reduce across 8 K-slice warps, leaky update, tanh, publish
        float* rnew = g_rbuf[(s & 1) ^ 1];
        for (int idx = tid; idx < 768; idx += NTH) {
            int col = idx >> 6, b = idx & 63, jj = col & 3;
            int e = b*4 + ((b >> 3) << 2) + jj;
            float sum = 0.f;
            if (col < 4) {            // m1: rows 4q+1 (a1,jg0), 4q+2 (a0,jg1)
                #pragma unroll
                for (int q = 0; q < 8; q++)
                    sum += red_s[(4*q+1)*288 + e] + red_s[(4*q+2)*288 + e];
            } else if (col < 8) {     // pmd: rows 4q (a0,jg0)
                #pragma unroll
                for (int q = 0; q < 8; q++) sum += red_s[(4*q+0)*288 + e];
            } else {                  // s1: rows 4q+3 (a1,jg1)
                #pragma unroll
                for (int q = 0; q < 8; q++) sum += red_s[(4*q+3)*288 + e];
            }
            float x = xs[idx];
            x = 0.9f*x + 0.1f*(sum + bias_s[col]);
            xs[idx] = x;
            float r = tanhf(x);
            int grow = (col < 4) ? (j0 + col)
                     : (col < 8) ? (512 + j0 + col - 4)
                                 : (1024 + j0 + col - 8);
            rnew[grow*64 + b] = r;
            if (col < 4) g_Rm1[(s*512 + j0 + col)*64 + b] = r;
        }

        // stage X(s+1) into own buf0 region (rides through the barrier window)
        if (s < 498) stage_x(in_s, g_XT + (s+1)*8192, ks, lane);

        __threadfence();
        __syncthreads();

        // split barrier: arrive ...
        if (tid == 0) {
            bar_old  = *(volatile unsigned*)&g_bar_gen;
            bar_prev = atomicAdd(&g_bar_count, 1u);
        }
        // ... overlap: compute X(s+1) contribution while other blocks arrive ...
        if (s < 498) {
            WAITG(0); __syncwarp();
            #pragma unroll
            for (int i = 0; i < 16; i++) a2[i] = 0.f;
            chunk_fma<16>(a2, rwp, wxc);
        }
        // ... release or wait
        if (tid == 0) {
            if (bar_prev == NB - 1u) {
                atomicExch(&g_bar_count, 0u);
                __threadfence();
                atomicAdd(&g_bar_gen, 1u);
            } else {
                while (*(volatile unsigned*)&g_bar_gen == bar_old) { }
            }
        }
        __syncthreads();
    }

    // ---- epilogue: out[t][b][o] = sum_k Rm1[t][k][b] * W_out[o][k] ----
    for (int i = tid; i < 5120; i += NTH) w_s[i] = W_out[i];
    for (int t = g; t < 499; t += NB) {
        float acc3[3] = {0.f, 0.f, 0.f};
        for (int h = 0; h < 2; h++) {
            __syncthreads();
            const float4* src = (const float4*)(g_Rm1 + (t*512 + h*256)*64);
            for (int i = tid; i < 4096; i += NTH) ((float4*)in_s)[i] = src[i];
            __syncthreads();
            #pragma unroll
            for (int pi = 0; pi < 3; pi++) {
                int p = tid + pi*256;
                if (p < 640) {
                    int o = p >> 6, b = p & 63;
                    float sv = 0.f;
                    #pragma unroll 8
                    for (int k = 0; k < 256; k++)
                        sv += in_s[k*64 + b] * w_s[o*512 + h*256 + k];
                    acc3[pi] += sv;
                }
            }
        }
        #pragma unroll
        for (int pi = 0; pi < 3; pi++) {
            int p = tid + pi*256;
            if (p < 640) {
                int o = p >> 6, b = p & 63;
                out[t*640 + b*10 + o] = acc3[pi];
            }
        }
    }
}

extern "C" void kernel_launch(void* const* d_in, const int* in_sizes, int n_in,
                              void* d_out, int out_size) {
    cudaFuncSetAttribute(rnn_kernel, cudaFuncAttributeMaxDynamicSharedMemorySize, SMEM_BYTES);
    rnn_kernel<<<NB, NTH, SMEM_BYTES>>>(
        (const float*)d_in[0],  (const float*)d_in[1],  (const float*)d_in[2],
        (const float*)d_in[3],  (const float*)d_in[4],  (const float*)d_in[5],
        (const float*)d_in[6],  (const float*)d_in[7],  (const float*)d_in[8],
        (const float*)d_in[9],  (const float*)d_in[10], (const float*)d_in[11],
        (const float*)d_in[12], (float*)d_out);
}

// round 9
// speedup vs baseline: 1.3207x; 1.0455x over previous
#include <cuda_runtime.h>
#include <cstdint>

#define NB   128
#define NTH  256

// SMEM float offsets
#define W_OFF    0        // 13312: weights [kabs 0..1663][8 slots]
#define IN_OFF   13312    // 32768: double-buffered 256k-chunk [2][256][64] (warp-private rows)
#define RED_OFF  46080    // 9216: reduction 32 rows x 288
#define XS_OFF   55296    // 768
#define BIAS_OFF 56064    // 16
#define BASE_OFF 56080    // 8 (counter base snapshot)
#define SMEM_FLOATS 56088
#define SMEM_BYTES  (SMEM_FLOATS*4)

__device__ float    g_rbuf[3][1536*64];   // rates, [k][b], 3 rotating buffers
__device__ float    g_XT[499*128*64];     // X transposed/padded: [s][d(128)][b]
__device__ float    g_Rm1[499*512*64];    // r_m1 history [s][k][b]
__device__ unsigned g_cnt[6*32];          // per-chunk produce counters, 128B apart
__device__ unsigned g_bar_count;
__device__ unsigned g_bar_gen;

__device__ __forceinline__ void cp16(float* sdst, const float* gsrc) {
    unsigned s = (unsigned)__cvta_generic_to_shared(sdst);
    asm volatile("cp.async.cg.shared.global [%0], [%1], 16;\n" :: "r"(s), "l"(gsrc) : "memory");
}
#define WAITG(n) asm volatile("cp.async.wait_group %0;\n" :: "n"(n) : "memory")
#define COMMIT   asm volatile("cp.async.commit_group;\n" ::: "memory")

// warp-private staging: warp ks copies its own 32 rows (2048 floats) of a chunk
__device__ __forceinline__ void stage_chunk(float* dstbuf, const float* srcchunk,
                                            int ks, int lane) {
    const float* src = srcchunk + ks*2048;
    float*       dst = dstbuf   + ks*2048;
    #pragma unroll
    for (int q = 0; q < 16; q++) { int i = q*32 + lane; cp16(dst + i*4, src + i*4); }
    COMMIT;
}
// X chunk: warp ks copies its 16 rows (1024 floats) into ITS OWN buffer region
__device__ __forceinline__ void stage_x(float* dstbuf, const float* srcx,
                                        int ks, int lane) {
    const float* src = srcx   + ks*1024;
    float*       dst = dstbuf + ks*2048;
    #pragma unroll
    for (int q = 0; q < 8; q++) { int i = q*32 + lane; cp16(dst + i*4, src + i*4); }
    COMMIT;
}

// spin until produce-counter m reaches tgt (monotonic, wrap-safe)
__device__ __forceinline__ void wait_cnt(int m, unsigned tgt) {
    const unsigned* p = &g_cnt[m*32];
    unsigned v;
    do { asm volatile("ld.acquire.gpu.u32 %0,[%1];" : "=r"(v) : "l"(p) : "memory"); }
    while ((int)(v - tgt) < 0);
}

// central-atomic grid barrier (init/epilogue only); monotonic gen, replay-safe
__device__ __forceinline__ void grid_barrier() {
    __syncthreads();
    if (threadIdx.x == 0) {
        __threadfence();
        unsigned old = *(volatile unsigned*)&g_bar_gen;
        if (atomicAdd(&g_bar_count, 1u) == NB - 1u) {
            atomicExch(&g_bar_count, 0u);
            __threadfence();
            atomicAdd(&g_bar_gen, 1u);
        } else {
            while (*(volatile unsigned*)&g_bar_gen == old) { }
        }
    }
    __syncthreads();
}

// KS k-iters; rin pre-offset to warp region (+b0), wc pre-offset to warp k-slice (+jg*4)
template<int KS>
__device__ __forceinline__ void chunk_fma(float (&acc)[16], const float* rin,
                                          const float* wc) {
    #pragma unroll
    for (int t = 0; t < KS; t++) {
        float4 rv = *(const float4*)(rin + t*64);
        float4 wv = *(const float4*)(wc + t*8);
        acc[0]  += rv.x*wv.x; acc[1]  += rv.x*wv.y; acc[2]  += rv.x*wv.z; acc[3]  += rv.x*wv.w;
        acc[4]  += rv.y*wv.x; acc[5]  += rv.y*wv.y; acc[6]  += rv.y*wv.z; acc[7]  += rv.y*wv.w;
        acc[8]  += rv.z*wv.x; acc[9]  += rv.z*wv.y; acc[10] += rv.z*wv.z; acc[11] += rv.z*wv.w;
        acc[12] += rv.w*wv.x; acc[13] += rv.w*wv.y; acc[14] += rv.w*wv.z; acc[15] += rv.w*wv.w;
    }
}

__global__ void __launch_bounds__(NTH, 1)
rnn_kernel(const float* __restrict__ X,
           const float* __restrict__ W_rec_m1, const float* __restrict__ W_rec_pmd,
           const float* __restrict__ W_rec_s1,
           const float* __restrict__ b_m1, const float* __restrict__ b_pmd,
           const float* __restrict__ b_s1,
           const float* __restrict__ W_pmd_m1, const float* __restrict__ W_s1_m1,
           const float* __restrict__ W_m1_pmd,
           const float* __restrict__ W_in_pmd, const float* __restrict__ W_in_s1,
           const float* __restrict__ W_out,
           float* __restrict__ out)
{
    extern __shared__ float sm[];
    const int tid = threadIdx.x;
    const int g   = blockIdx.x;
    float* w_s    = sm + W_OFF;
    float* in_s   = sm + IN_OFF;
    float* red_s  = sm + RED_OFF;
    float* xs     = sm + XS_OFF;
    float* bias_s = sm + BIAS_OFF;
    volatile unsigned* base_s = (volatile unsigned*)(sm + BASE_OFF);
    const int j0  = 4*g;
    const int gh  = (g >= 64) ? 1 : 0;

    // ---- phase 0: init globals ----
    for (int i = g*NTH + tid; i < 3*1536*64; i += NB*NTH) ((float*)g_rbuf)[i] = 0.f;
    for (int i = g*NTH + tid; i < 499*128*64; i += NB*NTH) {
        int b = i & 63, d = (i >> 6) & 127, s = i >> 13;
        g_XT[i] = (d < 100) ? X[((s+1)*64 + b)*100 + d] : 0.f;
    }

    // ---- weights into SMEM: w_s[kabs][slot], slot = jg*4+jj ----
    // kabs 0-511 (r_m1):     jg0=W_m1_pmd(->pmd) jg1=W_rec_m1(->m1)
    // kabs 512-1023 (r_pmd): jg0=W_rec_pmd(->pmd) jg1=W_pmd_m1(->m1)
    // kabs 1024-1535 (r_s1): jg0=W_s1_m1(->m1)   jg1=W_rec_s1(->s1)
    // kabs 1536-1663 (Xt):   jg0=W_in_pmd(->pmd) jg1=W_in_s1(->s1)
    for (int idx = tid; idx < 13312; idx += NTH) {
        int c = idx >> 10, rem = idx & 1023, k = rem >> 3, slot = rem & 7;
        int jgq = slot >> 2, jj = slot & 3;
        float v;
        if (c < 4) { int kk = c*128 + k;
            v = jgq ? W_rec_m1[(j0+jj)*512 + kk] : W_m1_pmd[(j0+jj)*512 + kk];
        } else if (c < 8) { int kk = (c-4)*128 + k;
            v = jgq ? W_pmd_m1[(j0+jj)*512 + kk] : W_rec_pmd[(j0+jj)*512 + kk];
        } else if (c < 12) { int kk = (c-8)*128 + k;
            v = jgq ? W_rec_s1[(j0+jj)*512 + kk] : W_s1_m1[(j0+jj)*512 + kk];
        } else {
            v = (k < 100) ? (jgq ? W_in_s1[(j0+jj)*100 + k] : W_in_pmd[(j0+jj)*100 + k]) : 0.f;
        }
        w_s[idx] = v;
    }
    if (tid < 12) {
        int jj = tid & 3;
        bias_s[tid] = (tid < 4) ? b_m1[j0+jj] : ((tid < 8) ? b_pmd[j0+jj] : b_s1[j0+jj]);
    }
    for (int i = tid; i < 768; i += NTH) xs[i] = 0.f;

    // snapshot counter bases BEFORE the barrier (no increments can be in flight)
    if (tid < 6) base_s[tid] = *(volatile unsigned*)&g_cnt[tid*32];

    grid_barrier();

    const int ks   = tid >> 5;          // 0..7 K-slices
    const int lane = tid & 31;
    const int jg   = lane >> 4;
    const int b0   = (lane & 15) * 4;
    const float* rwp = in_s + ks*2048 + b0;          // warp region in buf0
    const float* wxc = w_s + 12288 + ks*128 + jg*4;  // X weight slice

    // prologue: stage + compute X(0) contribution
    float a2[16];
    #pragma unroll
    for (int i = 0; i < 16; i++) a2[i] = 0.f;
    stage_x(in_s, g_XT, ks, lane);
    WAITG(0); __syncwarp();
    chunk_fma<16>(a2, rwp, wxc);

    // ---- the 499-step scan (no global barrier; chunk-granular flow control) ----
    int sm3 = 0;
    for (int s = 0; s < 499; s++) {
        const float* rb = g_rbuf[sm3];
        const int sn3 = (sm3 == 2) ? 0 : sm3 + 1;
        const unsigned step64 = 64u * (unsigned)s;

        float a0[16], a1[16];
        #pragma unroll
        for (int i = 0; i < 16; i++) { a0[i] = 0.f; a1[i] = 0.f; }

        // chunk c covers kabs [(c-1)*256, c*256); counter (c-1) gates staging
        wait_cnt(0, base_s[0] + step64);
        stage_chunk(in_s + 16384, rb, ks, lane);          // c1 -> buf1
        #pragma unroll
        for (int c = 1; c <= 6; c++) {
            if (c < 6) {
                wait_cnt(c, base_s[c] + step64);
                stage_chunk(in_s + (((c+1)&1)<<14), rb + c*16384, ks, lane);
                WAITG(1);
            } else {
                WAITG(0);
            }
            __syncwarp();
            const float* rin = in_s + ((c&1)<<14) + ks*2048 + b0;
            const float* wc  = w_s + (c-1)*2048 + ks*256 + jg*4;
            if (c <= 4) chunk_fma<32>(a0, rin, wc);
            else        chunk_fma<32>(a1, rin, wc);
        }

        // merge X contribution: jg0 -> pmd(a0), jg1 -> s1(a1)
        #pragma unroll
        for (int i = 0; i < 16; i++) {
            if (jg == 0) a0[i] += a2[i]; else a1[i] += a2[i];
        }

        // dump partials: red_s[row][e], row stride 288, e = b*4 + (b>>3)*4 (+jj)
        {
            const int rowP = 4*ks + 2*jg, rowS = rowP + 1;
            #pragma unroll
            for (int bi = 0; bi < 4; bi++) {
                int b = b0 + bi;
                int e = b*4 + ((b >> 3) << 2);
                *(float4*)(red_s + rowP*288 + e) = make_float4(a0[bi*4+0], a0[bi*4+1], a0[bi*4+2], a0[bi*4+3]);
                *(float4*)(red_s + rowS*288 + e) = make_float4(a1[bi*4+0], a1[bi*4+1], a1[bi*4+2], a1[bi*4+3]);
            }
        }
        __syncthreads();

        // reduce across 8 K-slice warps, leaky update, tanh, publish
        float* rnew = g_rbuf[sn3];
        for (int idx = tid; idx < 768; idx += NTH) {
            int col = idx >> 6, b = idx & 63, jj = col & 3;
            int e = b*4 + ((b >> 3) << 2) + jj;
            float sum = 0.f;
            if (col < 4) {            // m1: rows 4q+1 (a1,jg0), 4q+2 (a0,jg1)
                #pragma unroll
                for (int q = 0; q < 8; q++)
                    sum += red_s[(4*q+1)*288 + e] + red_s[(4*q+2)*288 + e];
            } else if (col < 8) {     // pmd: rows 4q (a0,jg0)
                #pragma unroll
                for (int q = 0; q < 8; q++) sum += red_s[(4*q+0)*288 + e];
            } else {                  // s1: rows 4q+3 (a1,jg1)
                #pragma unroll
                for (int q = 0; q < 8; q++) sum += red_s[(4*q+3)*288 + e];
            }
            float x = xs[idx];
            x = 0.9f*x + 0.1f*(sum + bias_s[col]);
            xs[idx] = x;
            float r = tanhf(x);
            int grow = (col < 4) ? (j0 + col)
                     : (col < 8) ? (512 + j0 + col - 4)
                                 : (1024 + j0 + col - 8);
            rnew[grow*64 + b] = r;
            if (col < 4) g_Rm1[(s*512 + j0 + col)*64 + b] = r;
        }
        __threadfence();
        __syncthreads();

        // publish: this block produced rows in chunks {1,3,5} (g<64) or {2,4,6}
        if (tid < 3) {
            int m = (tid << 1) + gh;
            asm volatile("red.release.gpu.global.add.u32 [%0],%1;"
                         :: "l"(&g_cnt[m*32]), "r"(1u) : "memory");
        }

        // stage + compute X(s+1) while frontier chunks are being produced
        if (s < 498) {
            stage_x(in_s, g_XT + (s+1)*8192, ks, lane);
            WAITG(0); __syncwarp();
            #pragma unroll
            for (int i = 0; i < 16; i++) a2[i] = 0.f;
            chunk_fma<16>(a2, rwp, wxc);
        }
        sm3 = sn3;
    }

    // all r_m1 history must be complete before the epilogue reads it
    grid_barrier();

    // ---- epilogue: out[t][b][o] = sum_k Rm1[t][k][b] * W_out[o][k] ----
    for (int i = tid; i < 5120; i += NTH) w_s[i] = W_out[i];
    for (int t = g; t < 499; t += NB) {
        float acc3[3] = {0.f, 0.f, 0.f};
        for (int h = 0; h < 2; h++) {
            __syncthreads();
            const float4* src = (const float4*)(g_Rm1 + (t*512 + h*256)*64);
            for (int i = tid; i < 4096; i += NTH) ((float4*)in_s)[i] = src[i];
            __syncthreads();
            #pragma unroll
            for (int pi = 0; pi < 3; pi++) {
                int p = tid + pi*256;
                if (p < 640) {
                    int o = p >> 6, b = p & 63;
                    float sv = 0.f;
                    #pragma unroll 8
                    for (int k = 0; k < 256; k++)
                        sv += in_s[k*64 + b] * w_s[o*512 + h*256 + k];
                    acc3[pi] += sv;
                }
            }
        }
        #pragma unroll
        for (int pi = 0; pi < 3; pi++) {
            int p = tid + pi*256;
            if (p < 640) {
                int o = p >> 6, b = p & 63;
                out[t*640 + b*10 + o] = acc3[pi];
            }
        }
    }
}

extern "C" void kernel_launch(void* const* d_in, const int* in_sizes, int n_in,
                              void* d_out, int out_size) {
    cudaFuncSetAttribute(rnn_kernel, cudaFuncAttributeMaxDynamicSharedMemorySize, SMEM_BYTES);
    rnn_kernel<<<NB, NTH, SMEM_BYTES>>>(
        (const float*)d_in[0],  (const float*)d_in[1],  (const float*)d_in[2],
        (const float*)d_in[3],  (const float*)d_in[4],  (const float*)d_in[5],
        (const float*)d_in[6],  (const float*)d_in[7],  (const float*)d_in[8],
        (const float*)d_in[9],  (const float*)d_in[10], (const float*)d_in[11],
        (const float*)d_in[12], (float*)d_out);
}

// round 13
// speedup vs baseline: 1.3939x; 1.0554x over previous
#include <cuda_runtime.h>
#include <cstdint>

#define NB   128
#define NTH  256

// SMEM float offsets
#define W_OFF    0        // 13312: weights [kabs 0..1663][8 slots]
#define IN_OFF   13312    // 32768: double-buffered 256k-chunk [2][256][64] (warp-private rows)
#define RED_OFF  46080    // 9216: reduction 32 rows x 288
#define XS_OFF   55296    // 768
#define BIAS_OFF 56064    // 16
#define BASE_OFF 56080    // 8 (counter base snapshot)
#define SMEM_FLOATS 56088
#define SMEM_BYTES  (SMEM_FLOATS*4)

__device__ float    g_rbuf[3][1536*64];   // rates, [k][b], 3 rotating buffers
__device__ float    g_XT[499*128*64];     // X transposed/padded: [s][d(128)][b]
__device__ float    g_Rm1[499*512*64];    // r_m1 history [s][k][b]
__device__ unsigned g_cnt[6*32];          // per-chunk produce counters, 128B apart
__device__ unsigned g_bar_count;
__device__ unsigned g_bar_gen;

__device__ __forceinline__ void cp16(float* sdst, const float* gsrc) {
    unsigned s = (unsigned)__cvta_generic_to_shared(sdst);
    asm volatile("cp.async.cg.shared.global [%0], [%1], 16;\n" :: "r"(s), "l"(gsrc) : "memory");
}
#define WAITG(n) asm volatile("cp.async.wait_group %0;\n" :: "n"(n) : "memory")
#define COMMIT   asm volatile("cp.async.commit_group;\n" ::: "memory")

// warp-private staging: warp ks copies its own 32 rows (2048 floats) of a chunk
__device__ __forceinline__ void stage_chunk(float* dstbuf, const float* srcchunk,
                                            int ks, int lane) {
    const float* src = srcchunk + ks*2048;
    float*       dst = dstbuf   + ks*2048;
    #pragma unroll
    for (int q = 0; q < 16; q++) { int i = q*32 + lane; cp16(dst + i*4, src + i*4); }
    COMMIT;
}
// X chunk: warp ks copies its 16 rows (1024 floats) into ITS OWN buffer region
__device__ __forceinline__ void stage_x(float* dstbuf, const float* srcx,
                                        int ks, int lane) {
    const float* src = srcx   + ks*1024;
    float*       dst = dstbuf + ks*2048;
    #pragma unroll
    for (int q = 0; q < 8; q++) { int i = q*32 + lane; cp16(dst + i*4, src + i*4); }
    COMMIT;
}

// spin until produce-counter m reaches tgt (monotonic, wrap-safe)
__device__ __forceinline__ void wait_cnt(int m, unsigned tgt) {
    const unsigned* p = &g_cnt[m*32];
    unsigned v;
    do { asm volatile("ld.acquire.gpu.u32 %0,[%1];" : "=r"(v) : "l"(p) : "memory"); }
    while ((int)(v - tgt) < 0);
}

// central-atomic grid barrier (init/epilogue only); monotonic gen, replay-safe
__device__ __forceinline__ void grid_barrier() {
    __syncthreads();
    if (threadIdx.x == 0) {
        __threadfence();
        unsigned old = *(volatile unsigned*)&g_bar_gen;
        if (atomicAdd(&g_bar_count, 1u) == NB - 1u) {
            atomicExch(&g_bar_count, 0u);
            __threadfence();
            atomicAdd(&g_bar_gen, 1u);
        } else {
            while (*(volatile unsigned*)&g_bar_gen == old) { }
        }
    }
    __syncthreads();
}

// KS k-iters; rin pre-offset to warp region (+b0), wc pre-offset to warp k-slice (+jg*4)
template<int KS>
__device__ __forceinline__ void chunk_fma(float (&acc)[16], const float* rin,
                                          const float* wc) {
    #pragma unroll
    for (int t = 0; t < KS; t++) {
        float4 rv = *(const float4*)(rin + t*64);
        float4 wv = *(const float4*)(wc + t*8);
        acc[0]  += rv.x*wv.x; acc[1]  += rv.x*wv.y; acc[2]  += rv.x*wv.z; acc[3]  += rv.x*wv.w;
        acc[4]  += rv.y*wv.x; acc[5]  += rv.y*wv.y; acc[6]  += rv.y*wv.z; acc[7]  += rv.y*wv.w;
        acc[8]  += rv.z*wv.x; acc[9]  += rv.z*wv.y; acc[10] += rv.z*wv.z; acc[11] += rv.z*wv.w;
        acc[12] += rv.w*wv.x; acc[13] += rv.w*wv.y; acc[14] += rv.w*wv.z; acc[15] += rv.w*wv.w;
    }
}

__global__ void __launch_bounds__(NTH, 1)
rnn_kernel(const float* __restrict__ X,
           const float* __restrict__ W_rec_m1, const float* __restrict__ W_rec_pmd,
           const float* __restrict__ W_rec_s1,
           const float* __restrict__ b_m1, const float* __restrict__ b_pmd,
           const float* __restrict__ b_s1,
           const float* __restrict__ W_pmd_m1, const float* __restrict__ W_s1_m1,
           const float* __restrict__ W_m1_pmd,
           const float* __restrict__ W_in_pmd, const float* __restrict__ W_in_s1,
           const float* __restrict__ W_out,
           float* __restrict__ out)
{
    extern __shared__ float sm[];
    const int tid = threadIdx.x;
    const int g   = blockIdx.x;
    float* w_s    = sm + W_OFF;
    float* in_s   = sm + IN_OFF;
    float* red_s  = sm + RED_OFF;
    float* xs     = sm + XS_OFF;
    float* bias_s = sm + BIAS_OFF;
    volatile unsigned* base_s = (volatile unsigned*)(sm + BASE_OFF);
    const int j0  = 4*g;
    const int gh  = (g >= 64) ? 1 : 0;

    // ---- phase 0: init globals ----
    for (int i = g*NTH + tid; i < 3*1536*64; i += NB*NTH) ((float*)g_rbuf)[i] = 0.f;
    for (int i = g*NTH + tid; i < 499*128*64; i += NB*NTH) {
        int b = i & 63, d = (i >> 6) & 127, s = i >> 13;
        g_XT[i] = (d < 100) ? X[((s+1)*64 + b)*100 + d] : 0.f;
    }

    // ---- weights into SMEM: w_s[kabs][slot], slot = jg*4+jj ----
    // kabs 0-511 (r_m1):     jg0=W_m1_pmd(->pmd) jg1=W_rec_m1(->m1)
    // kabs 512-1023 (r_pmd): jg0=W_rec_pmd(->pmd) jg1=W_pmd_m1(->m1)
    // kabs 1024-1535 (r_s1): jg0=W_s1_m1(->m1)   jg1=W_rec_s1(->s1)
    // kabs 1536-1663 (Xt):   jg0=W_in_pmd(->pmd) jg1=W_in_s1(->s1)
    for (int idx = tid; idx < 13312; idx += NTH) {
        int c = idx >> 10, rem = idx & 1023, k = rem >> 3, slot = rem & 7;
        int jgq = slot >> 2, jj = slot & 3;
        float v;
        if (c < 4) { int kk = c*128 + k;
            v = jgq ? W_rec_m1[(j0+jj)*512 + kk] : W_m1_pmd[(j0+jj)*512 + kk];
        } else if (c < 8) { int kk = (c-4)*128 + k;
            v = jgq ? W_pmd_m1[(j0+jj)*512 + kk] : W_rec_pmd[(j0+jj)*512 + kk];
        } else if (c < 12) { int kk = (c-8)*128 + k;
            v = jgq ? W_rec_s1[(j0+jj)*512 + kk] : W_s1_m1[(j0+jj)*512 + kk];
        } else {
            v = (k < 100) ? (jgq ? W_in_s1[(j0+jj)*100 + k] : W_in_pmd[(j0+jj)*100 + k]) : 0.f;
        }
        w_s[idx] = v;
    }
    if (tid < 12) {
        int jj = tid & 3;
        bias_s[tid] = (tid < 4) ? b_m1[j0+jj] : ((tid < 8) ? b_pmd[j0+jj] : b_s1[j0+jj]);
    }
    for (int i = tid; i < 768; i += NTH) xs[i] = 0.f;

    // snapshot counter bases BEFORE the barrier (no increments can be in flight)
    if (tid < 6) base_s[tid] = *(volatile unsigned*)&g_cnt[tid*32];

    grid_barrier();

    const int ks   = tid >> 5;          // 0..7 K-slices
    const int lane = tid & 31;
    const int jg   = lane >> 4;
    const int b0   = (lane & 15) * 4;
    const float* rwp = in_s + ks*2048 + b0;          // warp region in buf0
    const float* wxc = w_s + 12288 + ks*128 + jg*4;  // X weight slice

    // prologue: stage + compute X(0) contribution
    float a2[16];
    #pragma unroll
    for (int i = 0; i < 16; i++) a2[i] = 0.f;
    stage_x(in_s, g_XT, ks, lane);
    WAITG(0); __syncwarp();
    chunk_fma<16>(a2, rwp, wxc);

    // ---- the 499-step scan (no global barrier; chunk-granular flow control) ----
    int sm3 = 0;
    for (int s = 0; s < 499; s++) {
        const float* rb = g_rbuf[sm3];
        const int sn3 = (sm3 == 2) ? 0 : sm3 + 1;
        const unsigned step64 = 64u * (unsigned)s;

        float a0[16], a1[16];
        #pragma unroll
        for (int i = 0; i < 16; i++) { a0[i] = 0.f; a1[i] = 0.f; }

        // chunk c covers kabs [(c-1)*256, c*256); counter (c-1) gates staging
        wait_cnt(0, base_s[0] + step64);
        stage_chunk(in_s + 16384, rb, ks, lane);          // c1 -> buf1
        #pragma unroll
        for (int c = 1; c <= 6; c++) {
            if (c < 6) {
                wait_cnt(c, base_s[c] + step64);
                stage_chunk(in_s + (((c+1)&1)<<14), rb + c*16384, ks, lane);
                WAITG(1);
            } else {
                WAITG(0);
            }
            __syncwarp();
            const float* rin = in_s + ((c&1)<<14) + ks*2048 + b0;
            const float* wc  = w_s + (c-1)*2048 + ks*256 + jg*4;
            if (c <= 4) chunk_fma<32>(a0, rin, wc);
            else        chunk_fma<32>(a1, rin, wc);
        }

        // merge X contribution: jg0 -> pmd(a0), jg1 -> s1(a1)
        #pragma unroll
        for (int i = 0; i < 16; i++) {
            if (jg == 0) a0[i] += a2[i]; else a1[i] += a2[i];
        }

        // stage X(s+1) early into own buf0 region: latency overlaps the reduction
        if (s < 498) stage_x(in_s, g_XT + (s+1)*8192, ks, lane);

        // dump partials: red_s[row][e], row stride 288, e = b*4 + (b>>3)*4 (+jj)
        {
            const int rowP = 4*ks + 2*jg, rowS = rowP + 1;
            #pragma unroll
            for (int bi = 0; bi < 4; bi++) {
                int b = b0 + bi;
                int e = b*4 + ((b >> 3) << 2);
                *(float4*)(red_s + rowP*288 + e) = make_float4(a0[bi*4+0], a0[bi*4+1], a0[bi*4+2], a0[bi*4+3]);
                *(float4*)(red_s + rowS*288 + e) = make_float4(a1[bi*4+0], a1[bi*4+1], a1[bi*4+2], a1[bi*4+3]);
            }
        }
        __syncthreads();

        // split reduction: warps 0-1 do m1 + early publish; warps 2-5 do pmd/s1
        float* rnew = g_rbuf[sn3];
        if (tid < 64) {
            // m1: rows 4q+1 (a1,jg0) + 4q+2 (a0,jg1); one batch per thread
            int b = tid;
            int e = b*4 + ((b >> 3) << 2);
            float4 s4 = make_float4(0.f, 0.f, 0.f, 0.f);
            #pragma unroll
            for (int q = 0; q < 8; q++) {
                float4 u = *(const float4*)(red_s + (4*q+1)*288 + e);
                float4 v = *(const float4*)(red_s + (4*q+2)*288 + e);
                s4.x += u.x + v.x; s4.y += u.y + v.y;
                s4.z += u.z + v.z; s4.w += u.w + v.w;
            }
            float sums[4] = {s4.x, s4.y, s4.z, s4.w};
            #pragma unroll
            for (int jj = 0; jj < 4; jj++) {
                float x = xs[jj*64 + b];
                x = 0.9f*x + 0.1f*(sums[jj] + bias_s[jj]);
                xs[jj*64 + b] = x;
                float r = tanhf(x);
                rnew[(j0+jj)*64 + b] = r;
                g_Rm1[(s*512 + j0 + jj)*64 + b] = r;
            }
            asm volatile("bar.sync 1, 64;" ::: "memory");
            if (tid == 0)
                asm volatile("red.release.gpu.global.add.u32 [%0],%1;"
                             :: "l"(&g_cnt[gh*32]), "r"(1u) : "memory");
        } else if (tid < 192) {
            int reg = (tid >= 128) ? 1 : 0;    // 0=pmd (rows 4q), 1=s1 (rows 4q+3)
            int b = tid & 63;
            int e = b*4 + ((b >> 3) << 2);
            int rbase = reg ? 3 : 0;
            float4 s4 = make_float4(0.f, 0.f, 0.f, 0.f);
            #pragma unroll
            for (int q = 0; q < 8; q++) {
                float4 u = *(const float4*)(red_s + (4*q+rbase)*288 + e);
                s4.x += u.x; s4.y += u.y; s4.z += u.z; s4.w += u.w;
            }
            float sums[4] = {s4.x, s4.y, s4.z, s4.w};
            int colb  = 4 + reg*4;
            int growb = (reg ? 1024 : 512) + j0;
            #pragma unroll
            for (int jj = 0; jj < 4; jj++) {
                float x = xs[(colb+jj)*64 + b];
                x = 0.9f*x + 0.1f*(sums[jj] + bias_s[colb+jj]);
                xs[(colb+jj)*64 + b] = x;
                rnew[(growb+jj)*64 + b] = tanhf(x);
            }
        }
        __syncthreads();

        // publish pmd / s1 counters
        if (tid < 2) {
            int m = (tid ? 4 : 2) + gh;
            asm volatile("red.release.gpu.global.add.u32 [%0],%1;"
                         :: "l"(&g_cnt[m*32]), "r"(1u) : "memory");
        }

        // compute X(s+1) contribution (overlaps other blocks' tails)
        if (s < 498) {
            WAITG(0); __syncwarp();
            #pragma unroll
            for (int i = 0; i < 16; i++) a2[i] = 0.f;
            chunk_fma<16>(a2, rwp, wxc);
        }
        sm3 = sn3;
    }

    // all r_m1 history must be complete before the epilogue reads it
    grid_barrier();

    // ---- epilogue: out[t][b][o] = sum_k Rm1[t][k][b] * W_out[o][k] ----
    for (int i = tid; i < 5120; i += NTH) w_s[i] = W_out[i];
    for (int t = g; t < 499; t += NB) {
        float acc3[3] = {0.f, 0.f, 0.f};
        for (int h = 0; h < 2; h++) {
            __syncthreads();
            const float4* src = (const float4*)(g_Rm1 + (t*512 + h*256)*64);
            for (int i = tid; i < 4096; i += NTH) ((float4*)in_s)[i] = src[i];
            __syncthreads();
            #pragma unroll
            for (int pi = 0; pi < 3; pi++) {
                int p = tid + pi*256;
                if (p < 640) {
                    int o = p >> 6, b = p & 63;
                    float sv = 0.f;
                    #pragma unroll 8
                    for (int k = 0; k < 256; k++)
                        sv += in_s[k*64 + b] * w_s[o*512 + h*256 + k];
                    acc3[pi] += sv;
                }
            }
        }
        #pragma unroll
        for (int pi = 0; pi < 3; pi++) {
            int p = tid + pi*256;
            if (p < 640) {
                int o = p >> 6, b = p & 63;
                out[t*640 + b*10 + o] = acc3[pi];
            }
        }
    }
}

extern "C" void kernel_launch(void* const* d_in, const int* in_sizes, int n_in,
                              void* d_out, int out_size) {
    cudaFuncSetAttribute(rnn_kernel, cudaFuncAttributeMaxDynamicSharedMemorySize, SMEM_BYTES);
    rnn_kernel<<<NB, NTH, SMEM_BYTES>>>(
        (const float*)d_in[0],  (const float*)d_in[1],  (const float*)d_in[2],
        (const float*)d_in[3],  (const float*)d_in[4],  (const float*)d_in[5],
        (const float*)d_in[6],  (const float*)d_in[7],  (const float*)d_in[8],
        (const float*)d_in[9],  (const float*)d_in[10], (const float*)d_in[11],
        (const float*)d_in[12], (float*)d_out);
}

// round 15
// speedup vs baseline: 1.4519x; 1.0416x over previous
#include <cuda_runtime.h>
#include <cstdint>

#define NB   128
#define NTH  256

// SMEM float offsets
#define W_OFF    0        // 13312: weights [kabs 0..1663][8 slots]
#define IN_OFF   13312    // 32768: double-buffered 256k-chunk [2][256][64] (warp-private rows)
#define RED_OFF  46080    // 9216: reduction 32 rows x 288 (s1:0-7, m1:8-23, pmd:24-31)
#define XS_OFF   55296    // 768
#define BIAS_OFF 56064    // 16
#define BASE_OFF 56080    // 8 (counter base snapshot)
#define SMEM_FLOATS 56088
#define SMEM_BYTES  (SMEM_FLOATS*4)

__device__ float    g_rbuf[3][1536*64];   // rates, [k][b], 3 rotating buffers
__device__ float    g_XT[499*128*64];     // X transposed/padded: [s][d(128)][b]
__device__ float    g_Rm1[499*512*64];    // r_m1 history [s][k][b]
__device__ unsigned g_cnt[6*32];          // per-chunk produce counters, 128B apart
__device__ unsigned g_bar_count;
__device__ unsigned g_bar_gen;

__device__ __forceinline__ void cp16(float* sdst, const float* gsrc) {
    unsigned s = (unsigned)__cvta_generic_to_shared(sdst);
    asm volatile("cp.async.cg.shared.global [%0], [%1], 16;\n" :: "r"(s), "l"(gsrc) : "memory");
}
#define WAITG(n) asm volatile("cp.async.wait_group %0;\n" :: "n"(n) : "memory")
#define COMMIT   asm volatile("cp.async.commit_group;\n" ::: "memory")

// warp-private staging: warp ks copies its own 32 rows (2048 floats) of a chunk
__device__ __forceinline__ void stage_chunk(float* dstbuf, const float* srcchunk,
                                            int ks, int lane) {
    const float* src = srcchunk + ks*2048;
    float*       dst = dstbuf   + ks*2048;
    #pragma unroll
    for (int q = 0; q < 16; q++) { int i = q*32 + lane; cp16(dst + i*4, src + i*4); }
    COMMIT;
}
// X chunk: warp ks copies its 16 rows (1024 floats) into ITS OWN buffer region
__device__ __forceinline__ void stage_x(float* dstbuf, const float* srcx,
                                        int ks, int lane) {
    const float* src = srcx   + ks*1024;
    float*       dst = dstbuf + ks*2048;
    #pragma unroll
    for (int q = 0; q < 8; q++) { int i = q*32 + lane; cp16(dst + i*4, src + i*4); }
    COMMIT;
}

// spin until produce-counter m reaches tgt (monotonic, wrap-safe)
__device__ __forceinline__ void wait_cnt(int m, unsigned tgt) {
    const unsigned* p = &g_cnt[m*32];
    unsigned v;
    do { asm volatile("ld.acquire.gpu.u32 %0,[%1];" : "=r"(v) : "l"(p) : "memory"); }
    while ((int)(v - tgt) < 0);
}

// central-atomic grid barrier (init/epilogue only); monotonic gen, replay-safe
__device__ __forceinline__ void grid_barrier() {
    __syncthreads();
    if (threadIdx.x == 0) {
        __threadfence();
        unsigned old = *(volatile unsigned*)&g_bar_gen;
        if (atomicAdd(&g_bar_count, 1u) == NB - 1u) {
            atomicExch(&g_bar_count, 0u);
            __threadfence();
            atomicAdd(&g_bar_gen, 1u);
        } else {
            while (*(volatile unsigned*)&g_bar_gen == old) { }
        }
    }
    __syncthreads();
}

// KS k-iters; rin pre-offset to warp region (+b0), wc pre-offset to warp k-slice (+jg*4)
template<int KS>
__device__ __forceinline__ void chunk_fma(float (&acc)[16], const float* rin,
                                          const float* wc) {
    #pragma unroll
    for (int t = 0; t < KS; t++) {
        float4 rv = *(const float4*)(rin + t*64);
        float4 wv = *(const float4*)(wc + t*8);
        acc[0]  += rv.x*wv.x; acc[1]  += rv.x*wv.y; acc[2]  += rv.x*wv.z; acc[3]  += rv.x*wv.w;
        acc[4]  += rv.y*wv.x; acc[5]  += rv.y*wv.y; acc[6]  += rv.y*wv.z; acc[7]  += rv.y*wv.w;
        acc[8]  += rv.z*wv.x; acc[9]  += rv.z*wv.y; acc[10] += rv.z*wv.z; acc[11] += rv.z*wv.w;
        acc[12] += rv.w*wv.x; acc[13] += rv.w*wv.y; acc[14] += rv.w*wv.z; acc[15] += rv.w*wv.w;
    }
}

__global__ void __launch_bounds__(NTH, 1)
rnn_kernel(const float* __restrict__ X,
           const float* __restrict__ W_rec_m1, const float* __restrict__ W_rec_pmd,
           const float* __restrict__ W_rec_s1,
           const float* __restrict__ b_m1, const float* __restrict__ b_pmd,
           const float* __restrict__ b_s1,
           const float* __restrict__ W_pmd_m1, const float* __restrict__ W_s1_m1,
           const float* __restrict__ W_m1_pmd,
           const float* __restrict__ W_in_pmd, const float* __restrict__ W_in_s1,
           const float* __restrict__ W_out,
           float* __restrict__ out)
{
    extern __shared__ float sm[];
    const int tid = threadIdx.x;
    const int g   = blockIdx.x;
    float* w_s    = sm + W_OFF;
    float* in_s   = sm + IN_OFF;
    float* red_s  = sm + RED_OFF;
    float* xs     = sm + XS_OFF;
    float* bias_s = sm + BIAS_OFF;
    volatile unsigned* base_s = (volatile unsigned*)(sm + BASE_OFF);
    const int j0  = 4*g;
    const int gh  = (g >= 64) ? 1 : 0;

    // ---- phase 0: init globals ----
    for (int i = g*NTH + tid; i < 3*1536*64; i += NB*NTH) ((float*)g_rbuf)[i] = 0.f;
    for (int i = g*NTH + tid; i < 499*128*64; i += NB*NTH) {
        int b = i & 63, d = (i >> 6) & 127, s = i >> 13;
        g_XT[i] = (d < 100) ? X[((s+1)*64 + b)*100 + d] : 0.f;
    }

    // ---- weights into SMEM: w_s[kabs][slot], slot = jg*4+jj ----
    // kabs 0-511 (r_m1):     jg0=W_m1_pmd(->pmd) jg1=W_rec_m1(->m1)
    // kabs 512-1023 (r_pmd): jg0=W_rec_pmd(->pmd) jg1=W_pmd_m1(->m1)
    // kabs 1024-1535 (r_s1): jg0=W_s1_m1(->m1)   jg1=W_rec_s1(->s1)
    // kabs 1536-1663 (Xt):   jg0=W_in_pmd(->pmd) jg1=W_in_s1(->s1)
    for (int idx = tid; idx < 13312; idx += NTH) {
        int c = idx >> 10, rem = idx & 1023, k = rem >> 3, slot = rem & 7;
        int jgq = slot >> 2, jj = slot & 3;
        float v;
        if (c < 4) { int kk = c*128 + k;
            v = jgq ? W_rec_m1[(j0+jj)*512 + kk] : W_m1_pmd[(j0+jj)*512 + kk];
        } else if (c < 8) { int kk = (c-4)*128 + k;
            v = jgq ? W_pmd_m1[(j0+jj)*512 + kk] : W_rec_pmd[(j0+jj)*512 + kk];
        } else if (c < 12) { int kk = (c-8)*128 + k;
            v = jgq ? W_rec_s1[(j0+jj)*512 + kk] : W_s1_m1[(j0+jj)*512 + kk];
        } else {
            v = (k < 100) ? (jgq ? W_in_s1[(j0+jj)*100 + k] : W_in_pmd[(j0+jj)*100 + k]) : 0.f;
        }
        w_s[idx] = v;
    }
    if (tid < 12) {
        int jj = tid & 3;
        bias_s[tid] = (tid < 4) ? b_m1[j0+jj] : ((tid < 8) ? b_pmd[j0+jj] : b_s1[j0+jj]);
    }
    for (int i = tid; i < 768; i += NTH) xs[i] = 0.f;

    // snapshot counter bases BEFORE the barrier (no increments can be in flight)
    if (tid < 6) base_s[tid] = *(volatile unsigned*)&g_cnt[tid*32];

    grid_barrier();

    const int ks   = tid >> 5;          // 0..7 K-slices
    const int lane = tid & 31;
    const int jg   = lane >> 4;
    const int b0   = (lane & 15) * 4;
    const float* rwp = in_s + ks*2048 + b0;          // warp region in buf0
    const float* wxc = w_s + 12288 + ks*128 + jg*4;  // X weight slice

    // prologue: stage + compute X(0) contribution
    float a2[16];
    #pragma unroll
    for (int i = 0; i < 16; i++) a2[i] = 0.f;
    stage_x(in_s, g_XT, ks, lane);
    WAITG(0); __syncwarp();
    chunk_fma<16>(a2, rwp, wxc);

    // ---- the 499-step scan; chunk consumption order [5,6,1,2,3,4] ----
    int sm3 = 0;
    for (int s = 0; s < 499; s++) {
        const float* rb = g_rbuf[sm3];
        const int sn3 = (sm3 == 2) ? 0 : sm3 + 1;
        const unsigned step64 = 64u * (unsigned)s;
        float* rnew = g_rbuf[sn3];

        float a0[16], a1[16];
        #pragma unroll
        for (int i = 0; i < 16; i++) { a0[i] = 0.f; a1[i] = 0.f; }

        // --- chunks 5,6 (r_s1): a0 (jg0 -> m1-part, jg1 -> s1) ---
        wait_cnt(4, base_s[4] + step64);
        stage_chunk(in_s + 16384, rb + 4*16384, ks, lane);   // c5 -> buf1
        wait_cnt(5, base_s[5] + step64);
        stage_chunk(in_s,         rb + 5*16384, ks, lane);   // c6 -> buf0
        WAITG(1); __syncwarp();
        chunk_fma<32>(a0, in_s + 16384 + ks*2048 + b0, w_s + 4*2048 + ks*256 + jg*4);
        wait_cnt(0, base_s[0] + step64);
        stage_chunk(in_s + 16384, rb,           ks, lane);   // c1 -> buf1
        WAITG(1); __syncwarp();
        chunk_fma<32>(a0, in_s + ks*2048 + b0,         w_s + 5*2048 + ks*256 + jg*4);

        // --- s1 phase: jg1 merges X, dumps rows 0-7; warps 6-7 reduce+publish early ---
        if (jg == 1) {
            #pragma unroll
            for (int i = 0; i < 16; i++) a0[i] += a2[i];
            #pragma unroll
            for (int bi = 0; bi < 4; bi++) {
                int b = b0 + bi;
                int e = b*4 + ((b >> 3) << 2);
                *(float4*)(red_s + ks*288 + e) = make_float4(a0[bi*4+0], a0[bi*4+1], a0[bi*4+2], a0[bi*4+3]);
            }
        }
        __syncthreads();   // sync#1
        if (tid >= 192) {  // warps 6-7: s1 reduce
            int b = tid - 192;
            int e = b*4 + ((b >> 3) << 2);
            float4 s4 = make_float4(0.f, 0.f, 0.f, 0.f);
            #pragma unroll
            for (int q = 0; q < 8; q++) {
                float4 u = *(const float4*)(red_s + q*288 + e);
                s4.x += u.x; s4.y += u.y; s4.z += u.z; s4.w += u.w;
            }
            float sums[4] = {s4.x, s4.y, s4.z, s4.w};
            #pragma unroll
            for (int jj = 0; jj < 4; jj++) {
                float x = xs[(8+jj)*64 + b];
                x = 0.9f*x + 0.1f*(sums[jj] + bias_s[8+jj]);
                xs[(8+jj)*64 + b] = x;
                rnew[(1024 + j0 + jj)*64 + b] = tanhf(x);
            }
            asm volatile("bar.sync 3, 64;" ::: "memory");
            if (tid == 192)
                asm volatile("red.release.gpu.global.add.u32 [%0],%1;"
                             :: "l"(&g_cnt[(4+gh)*32]), "r"(1u) : "memory");
        }

        // --- chunks 1,2,3,4: a1 (jg0 -> pmd, jg1 -> m1) ---
        wait_cnt(1, base_s[1] + step64);
        stage_chunk(in_s,         rb + 1*16384, ks, lane);   // c2 -> buf0
        WAITG(1); __syncwarp();
        chunk_fma<32>(a1, in_s + 16384 + ks*2048 + b0, w_s + 0*2048 + ks*256 + jg*4);  // c1
        wait_cnt(2, base_s[2] + step64);
        stage_chunk(in_s + 16384, rb + 2*16384, ks, lane);   // c3 -> buf1
        WAITG(1); __syncwarp();
        chunk_fma<32>(a1, in_s + ks*2048 + b0,         w_s + 1*2048 + ks*256 + jg*4);  // c2
        wait_cnt(3, base_s[3] + step64);
        stage_chunk(in_s,         rb + 3*16384, ks, lane);   // c4 -> buf0
        WAITG(1); __syncwarp();
        chunk_fma<32>(a1, in_s + 16384 + ks*2048 + b0, w_s + 2*2048 + ks*256 + jg*4);  // c3
        WAITG(0); __syncwarp();
        chunk_fma<32>(a1, in_s + ks*2048 + b0,         w_s + 3*2048 + ks*256 + jg*4);  // c4

        // jg0 merges X into pmd
        if (jg == 0) {
            #pragma unroll
            for (int i = 0; i < 16; i++) a1[i] += a2[i];
        }

        // stage X(s+1) into own buf0 region: latency overlaps the end reduction
        if (s < 498) stage_x(in_s, g_XT + (s+1)*8192, ks, lane);

        // dump m1 (rows 8-23) and pmd (rows 24-31)
        #pragma unroll
        for (int bi = 0; bi < 4; bi++) {
            int b = b0 + bi;
            int e = b*4 + ((b >> 3) << 2);
            if (jg == 0) {
                *(float4*)(red_s + (8 + 2*ks)*288 + e) = make_float4(a0[bi*4+0], a0[bi*4+1], a0[bi*4+2], a0[bi*4+3]);
                *(float4*)(red_s + (24 + ks)*288 + e)  = make_float4(a1[bi*4+0], a1[bi*4+1], a1[bi*4+2], a1[bi*4+3]);
            } else {
                *(float4*)(red_s + (9 + 2*ks)*288 + e) = make_float4(a1[bi*4+0], a1[bi*4+1], a1[bi*4+2], a1[bi*4+3]);
            }
        }
        __syncthreads();   // sync#2

        if (tid < 64) {            // warps 0-1: m1 reduce + publish
            int b = tid;
            int e = b*4 + ((b >> 3) << 2);
            float4 s4 = make_float4(0.f, 0.f, 0.f, 0.f);
            #pragma unroll
            for (int q = 0; q < 8; q++) {
                float4 u = *(const float4*)(red_s + (8 + 2*q)*288 + e);
                float4 v = *(const float4*)(red_s + (9 + 2*q)*288 + e);
                s4.x += u.x + v.x; s4.y += u.y + v.y;
                s4.z += u.z + v.z; s4.w += u.w + v.w;
            }
            float sums[4] = {s4.x, s4.y, s4.z, s4.w};
            #pragma unroll
            for (int jj = 0; jj < 4; jj++) {
                float x = xs[jj*64 + b];
                x = 0.9f*x + 0.1f*(sums[jj] + bias_s[jj]);
                xs[jj*64 + b] = x;
                float r = tanhf(x);
                rnew[(j0+jj)*64 + b] = r;
                g_Rm1[(s*512 + j0 + jj)*64 + b] = r;
            }
            asm volatile("bar.sync 1, 64;" ::: "memory");
            if (tid == 0)
                asm volatile("red.release.gpu.global.add.u32 [%0],%1;"
                             :: "l"(&g_cnt[gh*32]), "r"(1u) : "memory");
        } else if (tid < 128) {    // warps 2-3: pmd reduce + publish
            int b = tid - 64;
            int e = b*4 + ((b >> 3) << 2);
            float4 s4 = make_float4(0.f, 0.f, 0.f, 0.f);
            #pragma unroll
            for (int q = 0; q < 8; q++) {
                float4 u = *(const float4*)(red_s + (24 + q)*288 + e);
                s4.x += u.x; s4.y += u.y; s4.z += u.z; s4.w += u.w;
            }
            float sums[4] = {s4.x, s4.y, s4.z, s4.w};
            #pragma unroll
            for (int jj = 0; jj < 4; jj++) {
                float x = xs[(4+jj)*64 + b];
                x = 0.9f*x + 0.1f*(sums[jj] + bias_s[4+jj]);
                xs[(4+jj)*64 + b] = x;
                rnew[(512 + j0 + jj)*64 + b] = tanhf(x);
            }
            asm volatile("bar.sync 2, 64;" ::: "memory");
            if (tid == 64)
                asm volatile("red.release.gpu.global.add.u32 [%0],%1;"
                             :: "l"(&g_cnt[(2+gh)*32]), "r"(1u) : "memory");
        }

        // compute X(s+1) contribution (per-warp; reducers catch up after)
        if (s < 498) {
            WAITG(0); __syncwarp();
            #pragma unroll
            for (int i = 0; i < 16; i++) a2[i] = 0.f;
            chunk_fma<16>(a2, rwp, wxc);
        }
        sm3 = sn3;
    }

    // all r_m1 history must be complete before the epilogue reads it
    grid_barrier();

    // ---- epilogue: out[t][b][o] = sum_k Rm1[t][k][b] * W_out[o][k] ----
    for (int i = tid; i < 5120; i += NTH) w_s[i] = W_out[i];
    for (int t = g; t < 499; t += NB) {
        float acc3[3] = {0.f, 0.f, 0.f};
        for (int h = 0; h < 2; h++) {
            __syncthreads();
            const float4* src = (const float4*)(g_Rm1 + (t*512 + h*256)*64);
            for (int i = tid; i < 4096; i += NTH) ((float4*)in_s)[i] = src[i];
            __syncthreads();
            #pragma unroll
            for (int pi = 0; pi < 3; pi++) {
                int p = tid + pi*256;
                if (p < 640) {
                    int o = p >> 6, b = p & 63;
                    float sv = 0.f;
                    #pragma unroll 8
                    for (int k = 0; k < 256; k++)
                        sv += in_s[k*64 + b] * w_s[o*512 + h*256 + k];
                    acc3[pi] += sv;
                }
            }
        }
        #pragma unroll
        for (int pi = 0; pi < 3; pi++) {
            int p = tid + pi*256;
            if (p < 640) {
                int o = p >> 6, b = p & 63;
                out[t*640 + b*10 + o] = acc3[pi];
            }
        }
    }
}

extern "C" void kernel_launch(void* const* d_in, const int* in_sizes, int n_in,
                              void* d_out, int out_size) {
    cudaFuncSetAttribute(rnn_kernel, cudaFuncAttributeMaxDynamicSharedMemorySize, SMEM_BYTES);
    rnn_kernel<<<NB, NTH, SMEM_BYTES>>>(
        (const float*)d_in[0],  (const float*)d_in[1],  (const float*)d_in[2],
        (const float*)d_in[3],  (const float*)d_in[4],  (const float*)d_in[5],
        (const float*)d_in[6],  (const float*)d_in[7],  (const float*)d_in[8],
        (const float*)d_in[9],  (const float*)d_in[10], (const float*)d_in[11],
        (const float*)d_in[12], (float*)d_out);
}